// round 4
// baseline (speedup 1.0000x reference)
#include <cuda_runtime.h>

#define NMAX 50000
#define EMAX 800000

// ---------------- scratch ----------------
__device__ __align__(16) int   g_ssrc[EMAX];
__device__ __align__(16) int   g_src[EMAX];
__device__ __align__(16) int   g_dst[EMAX];
__device__ __align__(16) int   g_hist[NMAX];
__device__ __align__(16) int   g_rowptr[NMAX + 1];
__device__ __align__(16) int   g_cnt[NMAX];
__device__ __align__(16) int   g_bsum[256];
__device__ __align__(16) int   g_boff[256];
__device__ int   g_is64;
__device__ __align__(16) float g_deg[NMAX];
__device__ __align__(16) float g_dinv[NMAX];
__device__ __align__(16) float g_dinvc[NMAX];
__device__ __align__(16) float g_el[NMAX];
__device__ __align__(16) float g_er[NMAX];
__device__ __align__(16) float g_m[NMAX];
__device__ __align__(16) float g_z[NMAX];
__device__ __align__(16) float g_nsum[NMAX * 64];
__device__ __align__(16) float g_xw[NMAX * 64];
__device__ __align__(16) float g_h[NMAX * 64];
__device__ __align__(16) float g_accsage[NMAX * 64];
__device__ __align__(16) float g_accgin[NMAX * 64];
__device__ __align__(16) float g_accgcn[NMAX * 64];
__device__ __align__(16) float g_t1[NMAX * 64];
__device__ __align__(16) float g_t2[NMAX * 64];
__device__ __align__(16) float g_accgat[NMAX * 64];

// ---------------- helpers ----------------
__device__ __forceinline__ float eluf(float v) { return v > 0.f ? v : expm1f(v); }
__device__ __forceinline__ float leakyf(float v) { return v > 0.f ? v : 0.2f * v; }

__device__ __forceinline__ void hred(float4& v) {
    v.x += __shfl_xor_sync(0xffffffffu, v.x, 16);
    v.y += __shfl_xor_sync(0xffffffffu, v.y, 16);
    v.z += __shfl_xor_sync(0xffffffffu, v.z, 16);
    v.w += __shfl_xor_sync(0xffffffffu, v.w, 16);
}

// load 64x64 fp32 matrix into smem (256 threads)
__device__ __forceinline__ void loadW(float* Wsm, const float* __restrict__ Wg, int t) {
    const float4* s = (const float4*)Wg;
    float4* d = (float4*)Wsm;
#pragma unroll
    for (int i = 0; i < 4; i++) d[t + i * 256] = s[t + i * 256];
}

__device__ __forceinline__ void gemv16(const float* __restrict__ Wsm,
                                       const float4* __restrict__ Xs,
                                       int tt, int jbase, float acc[16]) {
#pragma unroll 4
    for (int k4 = 0; k4 < 16; k4++) {
        float4 xq = Xs[k4 * 128 + tt];
        const float* wr = Wsm + (k4 * 4) * 64 + jbase;
#pragma unroll
        for (int s = 0; s < 4; s++) {
            float xv = (s == 0) ? xq.x : (s == 1) ? xq.y : (s == 2) ? xq.z : xq.w;
            const float4* wp = (const float4*)(wr + s * 64);
            float4 w0 = wp[0], w1 = wp[1], w2 = wp[2], w3 = wp[3];
            acc[0]  += xv * w0.x; acc[1]  += xv * w0.y; acc[2]  += xv * w0.z; acc[3]  += xv * w0.w;
            acc[4]  += xv * w1.x; acc[5]  += xv * w1.y; acc[6]  += xv * w1.z; acc[7]  += xv * w1.w;
            acc[8]  += xv * w2.x; acc[9]  += xv * w2.y; acc[10] += xv * w2.z; acc[11] += xv * w2.w;
            acc[12] += xv * w3.x; acc[13] += xv * w3.y; acc[14] += xv * w3.z; acc[15] += xv * w3.w;
        }
    }
}

__device__ __forceinline__ void loadXs(float4* Xs, const float4* __restrict__ row,
                                       int tt, int half) {
#pragma unroll
    for (int i = 0; i < 8; i++) {
        int k4 = half * 8 + i;
        Xs[k4 * 128 + tt] = row[k4];
    }
}

// ---------------- CSR build ----------------
__global__ void kinit(const int* __restrict__ raw, int N) {
    int i = blockIdx.x * blockDim.x + threadIdx.x;
    if (i < N) g_hist[i] = 0;
    if (i == 0) {
        int acc = 0;
        for (int k = 0; k < 64; k++) acc |= raw[2 * k + 1];
        g_is64 = (acc == 0) ? 1 : 0;
    }
}

__global__ void kconvert(const void* __restrict__ raw, int E) {
    int is64 = g_is64;
    for (int e = blockIdx.x * blockDim.x + threadIdx.x; e < E;
         e += gridDim.x * blockDim.x) {
        int s, d;
        if (is64) {
            const long long* p = (const long long*)raw;
            s = (int)p[e];
            d = (int)p[(size_t)E + e];
        } else {
            const int* p = (const int*)raw;
            s = p[e];
            d = p[E + e];
        }
        g_src[e] = s;
        g_dst[e] = d;
        atomicAdd(&g_hist[d], 1);
    }
}

__global__ __launch_bounds__(256) void kbsum(int N) {
    __shared__ int red[256];
    int t = threadIdx.x;
    int i = blockIdx.x * 256 + t;
    red[t] = (i < N) ? g_hist[i] : 0;
    __syncthreads();
    for (int o = 128; o; o >>= 1) {
        if (t < o) red[t] += red[t + o];
        __syncthreads();
    }
    if (t == 0) g_bsum[blockIdx.x] = red[0];
}

__global__ __launch_bounds__(256) void kbscan(int G) {
    __shared__ int s[256];
    int t = threadIdx.x;
    int v = (t < G) ? g_bsum[t] : 0;
    s[t] = v;
    __syncthreads();
    for (int o = 1; o < 256; o <<= 1) {
        int u = (t >= o) ? s[t - o] : 0;
        __syncthreads();
        s[t] += u;
        __syncthreads();
    }
    if (t < G) g_boff[t] = s[t] - v;
}

__global__ __launch_bounds__(256) void kapply(int N, int E) {
    __shared__ int wsum[8];
    int t = threadIdx.x;
    int lane = t & 31, wid = t >> 5;
    int i = blockIdx.x * 256 + t;
    int h = (i < N) ? g_hist[i] : 0;
    int val = h;
#pragma unroll
    for (int o = 1; o < 32; o <<= 1) {
        int u = __shfl_up_sync(0xffffffffu, val, o);
        if (lane >= o) val += u;
    }
    if (lane == 31) wsum[wid] = val;
    __syncthreads();
    if (t < 8) {
        int w = wsum[t];
#pragma unroll
        for (int o = 1; o < 8; o <<= 1) {
            int u = __shfl_up_sync(0xffu, w, o);
            if (t >= o) w += u;
        }
        wsum[t] = w;
    }
    __syncthreads();
    int excl = val - h + (wid ? wsum[wid - 1] : 0) + g_boff[blockIdx.x];
    if (i < N) {
        g_rowptr[i] = excl;
        g_cnt[i] = excl;
        float deg = (float)h;
        g_deg[i] = deg;
        g_dinv[i] = rsqrtf(deg + 1.f);
        g_dinvc[i] = rsqrtf(fmaxf(deg, 1.f));
    }
    if (i == 0) g_rowptr[N] = E;
}

__global__ void kscatter(int E) {
    int e = blockIdx.x * blockDim.x + threadIdx.x;
    if (e >= E) return;
    int d = g_dst[e];
    int pos = atomicAdd(&g_cnt[d], 1);
    g_ssrc[pos] = g_src[e];
}

// ---------------- node kernel 1a: all x-based GEMVs ----------------
__global__ __launch_bounds__(256) void k1a(
    const float* __restrict__ x, const float* __restrict__ wts,
    const float* __restrict__ Wmlp, const float* __restrict__ bmlp,
    const float* __restrict__ Wgcn,
    const float* __restrict__ Wgat, const float* __restrict__ asrc,
    const float* __restrict__ adst,
    const float* __restrict__ Wr, const float* __restrict__ bsage,
    const float* __restrict__ Wgin, const float* __restrict__ bgin,
    float* __restrict__ out, int N) {
    __shared__ __align__(16) float Wsm[4096];
    __shared__ float4 Xs[2048];
    __shared__ float els[128], ers[128];
    int t = threadIdx.x;
    int tt = t & 127, half = t >> 7;
    int node = blockIdx.x * 128 + tt;
    bool act = node < N;
    if (act) loadXs(Xs, (const float4*)(x + (size_t)node * 64), tt, half);
    // --- W_mlp ---
    loadW(Wsm, Wmlp, t);
    __syncthreads();
    if (act) {
        float w0 = wts[0];
        float4* o4 = (float4*)(out + (size_t)node * 64);
#pragma unroll
        for (int c = 0; c < 2; c++) {
            int cc = half * 2 + c;
            float acc[16];
#pragma unroll
            for (int j = 0; j < 16; j++) acc[j] = bmlp[cc * 16 + j];
            gemv16(Wsm, Xs, tt, cc * 16, acc);
#pragma unroll
            for (int j = 0; j < 4; j++)
                o4[cc * 4 + j] = make_float4(w0 * eluf(acc[4 * j + 0]),
                                             w0 * eluf(acc[4 * j + 1]),
                                             w0 * eluf(acc[4 * j + 2]),
                                             w0 * eluf(acc[4 * j + 3]));
        }
    }
    __syncthreads();
    // --- W_gcn ---
    loadW(Wsm, Wgcn, t);
    __syncthreads();
    if (act) {
        float4* o4 = (float4*)(g_xw + (size_t)node * 64);
#pragma unroll
        for (int c = 0; c < 2; c++) {
            int cc = half * 2 + c;
            float acc[16] = {};
            gemv16(Wsm, Xs, tt, cc * 16, acc);
#pragma unroll
            for (int j = 0; j < 4; j++)
                o4[cc * 4 + j] = make_float4(acc[4 * j], acc[4 * j + 1],
                                             acc[4 * j + 2], acc[4 * j + 3]);
        }
    }
    __syncthreads();
    // --- W_gat ---
    loadW(Wsm, Wgat, t);
    __syncthreads();
    {
        float el = 0.f, er = 0.f;
        if (act) {
            float4* o4 = (float4*)(g_h + (size_t)node * 64);
#pragma unroll
            for (int c = 0; c < 2; c++) {
                int cc = half * 2 + c;
                float acc[16] = {};
                gemv16(Wsm, Xs, tt, cc * 16, acc);
#pragma unroll
                for (int j = 0; j < 16; j++) {
                    el += acc[j] * asrc[cc * 16 + j];
                    er += acc[j] * adst[cc * 16 + j];
                }
#pragma unroll
                for (int j = 0; j < 4; j++)
                    o4[cc * 4 + j] = make_float4(acc[4 * j], acc[4 * j + 1],
                                                 acc[4 * j + 2], acc[4 * j + 3]);
            }
        }
        if (half == 1) { els[tt] = el; ers[tt] = er; }
        __syncthreads();
        if (half == 0 && act) {
            g_el[node] = el + els[tt];
            g_er[node] = er + ers[tt];
        }
    }
    __syncthreads();
    // --- Wr_sage ---
    loadW(Wsm, Wr, t);
    __syncthreads();
    if (act) {
        float4* o4 = (float4*)(g_accsage + (size_t)node * 64);
#pragma unroll
        for (int c = 0; c < 2; c++) {
            int cc = half * 2 + c;
            float acc[16];
#pragma unroll
            for (int j = 0; j < 16; j++) acc[j] = bsage[cc * 16 + j];
            gemv16(Wsm, Xs, tt, cc * 16, acc);
#pragma unroll
            for (int j = 0; j < 4; j++)
                o4[cc * 4 + j] = make_float4(acc[4 * j], acc[4 * j + 1],
                                             acc[4 * j + 2], acc[4 * j + 3]);
        }
    }
    __syncthreads();
    // --- W_gin ---
    loadW(Wsm, Wgin, t);
    __syncthreads();
    if (act) {
        float4* o4 = (float4*)(g_accgin + (size_t)node * 64);
#pragma unroll
        for (int c = 0; c < 2; c++) {
            int cc = half * 2 + c;
            float acc[16];
#pragma unroll
            for (int j = 0; j < 16; j++) acc[j] = bgin[cc * 16 + j];
            gemv16(Wsm, Xs, tt, cc * 16, acc);
#pragma unroll
            for (int j = 0; j < 4; j++)
                o4[cc * 4 + j] = make_float4(acc[4 * j], acc[4 * j + 1],
                                             acc[4 * j + 2], acc[4 * j + 3]);
        }
    }
}

// ---------------- gather pass A: nsum + gcn + T1 + full GAT softmax ---------
// warp per node; two edges in flight (half-warp each, float4 per lane)
__global__ __launch_bounds__(256) void kaggA(const float* __restrict__ x, int N) {
    int gw = (blockIdx.x * 256 + threadIdx.x) >> 5;
    if (gw >= N) return;
    int lane = threadIdx.x & 31;
    int half = lane >> 4, hl = lane & 15;
    int d = gw;
    int beg = g_rowptr[d], end = g_rowptr[d + 1];
    float erd = g_er[d];
    float dinvd = g_dinv[d], dinvcd = g_dinvc[d];
    float es = leakyf(g_el[d] + erd);
    float m = es;
    for (int e = beg + lane; e < end; e += 32)
        m = fmaxf(m, leakyf(g_el[g_ssrc[e]] + erd));
#pragma unroll
    for (int o = 16; o; o >>= 1) m = fmaxf(m, __shfl_xor_sync(0xffffffffu, m, o));

    float4 ns = {0, 0, 0, 0}, gc = {0, 0, 0, 0}, t1 = {0, 0, 0, 0}, ga = {0, 0, 0, 0};
    float zacc = 0.f;
    for (int base = beg; base < end; base += 32) {
        int n = min(32, end - base);
        int sj = 0;
        float pj = 0.f, wgj = 0.f, wtj = 0.f;
        if (lane < n) {
            sj = g_ssrc[base + lane];
            pj = expf(leakyf(g_el[sj] + erd) - m);
            wgj = g_dinv[sj] * dinvd;
            wtj = g_dinvc[sj] * dinvcd;
            zacc += pj;
        }
        for (int j2 = 0; j2 < n; j2 += 2) {
            int j = (j2 + half) & 31;
            int s  = __shfl_sync(0xffffffffu, sj, j);
            float p  = __shfl_sync(0xffffffffu, pj, j);
            float wg = __shfl_sync(0xffffffffu, wgj, j);
            float wt = __shfl_sync(0xffffffffu, wtj, j);
            if (j2 + half < n) {
                float4 xv  = ((const float4*)(x    + (size_t)s * 64))[hl];
                float4 xwv = ((const float4*)(g_xw + (size_t)s * 64))[hl];
                float4 hv  = ((const float4*)(g_h  + (size_t)s * 64))[hl];
                ns.x += xv.x;       ns.y += xv.y;       ns.z += xv.z;       ns.w += xv.w;
                t1.x -= wt * xv.x;  t1.y -= wt * xv.y;  t1.z -= wt * xv.z;  t1.w -= wt * xv.w;
                gc.x += wg * xwv.x; gc.y += wg * xwv.y; gc.z += wg * xwv.z; gc.w += wg * xwv.w;
                ga.x += p * hv.x;   ga.y += p * hv.y;   ga.z += p * hv.z;   ga.w += p * hv.w;
            }
        }
    }
    hred(ns); hred(gc); hred(t1); hred(ga);
#pragma unroll
    for (int o = 16; o; o >>= 1) zacc += __shfl_xor_sync(0xffffffffu, zacc, o);
    float z = expf(es - m) + zacc;
    float invz = 1.f / (z + 1e-16f);
    if (half == 0) {
        ((float4*)(g_nsum   + (size_t)d * 64))[hl] = ns;
        ((float4*)(g_accgcn + (size_t)d * 64))[hl] = gc;
        ((float4*)(g_t1     + (size_t)d * 64))[hl] = t1;
        ((float4*)(g_accgat + (size_t)d * 64))[hl] =
            make_float4(ga.x * invz, ga.y * invz, ga.z * invz, ga.w * invz);
        if (lane == 0) { g_m[d] = m; g_z[d] = z; }
    }
}

// ---------------- gather pass B: Cheb T2 acc = prop(T1) ----------------
__global__ __launch_bounds__(256) void kaggB(int N) {
    int gw = (blockIdx.x * 256 + threadIdx.x) >> 5;
    if (gw >= N) return;
    int lane = threadIdx.x & 31;
    int half = lane >> 4, hl = lane & 15;
    int d = gw;
    int beg = g_rowptr[d], end = g_rowptr[d + 1];
    float dinvcd = g_dinvc[d];
    float4 t2 = {0, 0, 0, 0};
    for (int base = beg; base < end; base += 32) {
        int n = min(32, end - base);
        int sj = 0;
        float wtj = 0.f;
        if (lane < n) {
            sj = g_ssrc[base + lane];
            wtj = g_dinvc[sj] * dinvcd;
        }
        for (int j2 = 0; j2 < n; j2 += 2) {
            int j = (j2 + half) & 31;
            int s   = __shfl_sync(0xffffffffu, sj, j);
            float wt = __shfl_sync(0xffffffffu, wtj, j);
            if (j2 + half < n) {
                float4 v = ((const float4*)(g_t1 + (size_t)s * 64))[hl];
                t2.x += wt * v.x; t2.y += wt * v.y; t2.z += wt * v.z; t2.w += wt * v.w;
            }
        }
    }
    hred(t2);
    if (half == 0)
        ((float4*)(g_t2 + (size_t)d * 64))[hl] = t2;
}

// ---------------- fused final node kernel: sage + gin + cheb + gcn + gat ----
__global__ __launch_bounds__(256) void kfin(
    const float* __restrict__ x, const float* __restrict__ wts,
    const float* __restrict__ Wl, const float* __restrict__ Wgin,
    const float* __restrict__ Wcheb, const float* __restrict__ bcheb,
    const float* __restrict__ bgcn, const float* __restrict__ bgat,
    float* __restrict__ out, int N) {
    __shared__ __align__(16) float Wsm[4096];
    __shared__ float4 Xs[2048];
    int t = threadIdx.x;
    int tt = t & 127, half = t >> 7;
    int node = blockIdx.x * 128 + tt;
    bool act = node < N;
    float invd = 1.f;
    // phase 1: sage on nsum
    if (act) {
        loadXs(Xs, (const float4*)(g_nsum + (size_t)node * 64), tt, half);
        invd = 1.f / fmaxf(g_deg[node], 1.f);
    }
    loadW(Wsm, Wl, t);
    __syncthreads();
    if (act) {
        float w1 = wts[1];
        float4* o4 = (float4*)(out + (size_t)node * 64);
        const float4* as4 = (const float4*)(g_accsage + (size_t)node * 64);
#pragma unroll
        for (int c = 0; c < 2; c++) {
            int cc = half * 2 + c;
            float acc[16] = {};
            gemv16(Wsm, Xs, tt, cc * 16, acc);
#pragma unroll
            for (int j = 0; j < 4; j++) {
                float4 ov = o4[cc * 4 + j];
                float4 as = as4[cc * 4 + j];
                ov.x += w1 * eluf(acc[4 * j + 0] * invd + as.x);
                ov.y += w1 * eluf(acc[4 * j + 1] * invd + as.y);
                ov.z += w1 * eluf(acc[4 * j + 2] * invd + as.z);
                ov.w += w1 * eluf(acc[4 * j + 3] * invd + as.w);
                o4[cc * 4 + j] = ov;
            }
        }
    }
    __syncthreads();
    // phase 2: gin on nsum (Xs unchanged)
    loadW(Wsm, Wgin, t);
    __syncthreads();
    if (act) {
        float w5 = wts[5];
        float4* o4 = (float4*)(out + (size_t)node * 64);
        const float4* gi4 = (const float4*)(g_accgin + (size_t)node * 64);
#pragma unroll
        for (int c = 0; c < 2; c++) {
            int cc = half * 2 + c;
            float acc[16] = {};
            gemv16(Wsm, Xs, tt, cc * 16, acc);
#pragma unroll
            for (int j = 0; j < 4; j++) {
                float4 ov = o4[cc * 4 + j];
                float4 gi = gi4[cc * 4 + j];
                ov.x += w5 * eluf(acc[4 * j + 0] + gi.x);
                ov.y += w5 * eluf(acc[4 * j + 1] + gi.y);
                ov.z += w5 * eluf(acc[4 * j + 2] + gi.z);
                ov.w += w5 * eluf(acc[4 * j + 3] + gi.w);
                o4[cc * 4 + j] = ov;
            }
        }
    }
    __syncthreads();
    // phase 3: cheb T0 = x
    float cacc[32];
    if (act) loadXs(Xs, (const float4*)(x + (size_t)node * 64), tt, half);
    loadW(Wsm, Wcheb, t);
    __syncthreads();
    if (act) {
#pragma unroll
        for (int c = 0; c < 2; c++) {
            int cc = half * 2 + c;
            float acc[16];
#pragma unroll
            for (int j = 0; j < 16; j++) acc[j] = bcheb[cc * 16 + j];
            gemv16(Wsm, Xs, tt, cc * 16, acc);
#pragma unroll
            for (int j = 0; j < 16; j++) cacc[c * 16 + j] = acc[j];
        }
    }
    __syncthreads();
    // phase 4: cheb T1
    if (act) loadXs(Xs, (const float4*)(g_t1 + (size_t)node * 64), tt, half);
    loadW(Wsm, Wcheb + 4096, t);
    __syncthreads();
    if (act) {
#pragma unroll
        for (int c = 0; c < 2; c++) {
            int cc = half * 2 + c;
            float acc[16] = {};
            gemv16(Wsm, Xs, tt, cc * 16, acc);
#pragma unroll
            for (int j = 0; j < 16; j++) cacc[c * 16 + j] += acc[j];
        }
    }
    __syncthreads();
    // phase 5: cheb T2 = -2*prop(T1) - x, plus gcn/gat epilogue
    if (act) {
        const float4* xr = (const float4*)(x + (size_t)node * 64);
        const float4* t2r = (const float4*)(g_t2 + (size_t)node * 64);
#pragma unroll
        for (int i = 0; i < 8; i++) {
            int k4 = half * 8 + i;
            float4 a = xr[k4];
            float4 b = t2r[k4];
            Xs[k4 * 128 + tt] = make_float4(-2.f * b.x - a.x, -2.f * b.y - a.y,
                                            -2.f * b.z - a.z, -2.f * b.w - a.w);
        }
    }
    loadW(Wsm, Wcheb + 8192, t);
    __syncthreads();
    if (act) {
        float w2 = wts[2], w3 = wts[3], w4 = wts[4];
        float dinv = g_dinv[node];
        float di2 = dinv * dinv;
        float es = leakyf(g_el[node] + g_er[node]);
        float cs = expf(es - g_m[node]) / (g_z[node] + 1e-16f);
        const float4* gc4 = (const float4*)(g_accgcn + (size_t)node * 64);
        const float4* xw4 = (const float4*)(g_xw + (size_t)node * 64);
        const float4* ga4 = (const float4*)(g_accgat + (size_t)node * 64);
        const float4* h4 = (const float4*)(g_h + (size_t)node * 64);
        float4* o4 = (float4*)(out + (size_t)node * 64);
#pragma unroll
        for (int c = 0; c < 2; c++) {
            int cc = half * 2 + c;
            float acc[16] = {};
            gemv16(Wsm, Xs, tt, cc * 16, acc);
#pragma unroll
            for (int j = 0; j < 4; j++) {
                float4 gc = gc4[cc * 4 + j];
                float4 xwv = xw4[cc * 4 + j];
                float4 ga = ga4[cc * 4 + j];
                float4 hv = h4[cc * 4 + j];
                float4 bg = ((const float4*)bgcn)[cc * 4 + j];
                float4 bt = ((const float4*)bgat)[cc * 4 + j];
                float4 ov = o4[cc * 4 + j];
                ov.x += w2 * eluf(gc.x + xwv.x * di2 + bg.x)
                      + w3 * eluf(ga.x + cs * hv.x + bt.x)
                      + w4 * eluf(cacc[c * 16 + 4 * j + 0] + acc[4 * j + 0]);
                ov.y += w2 * eluf(gc.y + xwv.y * di2 + bg.y)
                      + w3 * eluf(ga.y + cs * hv.y + bt.y)
                      + w4 * eluf(cacc[c * 16 + 4 * j + 1] + acc[4 * j + 1]);
                ov.z += w2 * eluf(gc.z + xwv.z * di2 + bg.z)
                      + w3 * eluf(ga.z + cs * hv.z + bt.z)
                      + w4 * eluf(cacc[c * 16 + 4 * j + 2] + acc[4 * j + 2]);
                ov.w += w2 * eluf(gc.w + xwv.w * di2 + bg.w)
                      + w3 * eluf(ga.w + cs * hv.w + bt.w)
                      + w4 * eluf(cacc[c * 16 + 4 * j + 3] + acc[4 * j + 3]);
                o4[cc * 4 + j] = ov;
            }
        }
    }
}

// ---------------- host launcher ----------------
extern "C" void kernel_launch(void* const* d_in, const int* in_sizes, int n_in,
                              void* d_out, int out_size) {
    const float* x     = (const float*)d_in[0];
    const float* wts   = (const float*)d_in[1];
    const float* Wmlp  = (const float*)d_in[2];
    const float* bmlp  = (const float*)d_in[3];
    const float* Wl    = (const float*)d_in[4];
    const float* Wr    = (const float*)d_in[5];
    const float* bsage = (const float*)d_in[6];
    const float* Wgcn  = (const float*)d_in[7];
    const float* bgcn  = (const float*)d_in[8];
    const float* Wgat  = (const float*)d_in[9];
    const float* asrc  = (const float*)d_in[10];
    const float* adst  = (const float*)d_in[11];
    const float* bgat  = (const float*)d_in[12];
    const float* Wcheb = (const float*)d_in[13];
    const float* bcheb = (const float*)d_in[14];
    const float* Wgin  = (const float*)d_in[15];
    const float* bgin  = (const float*)d_in[16];
    const void*  eidx  = d_in[17];
    float* out = (float*)d_out;

    int N = in_sizes[0] / 64;
    if (N > NMAX) N = NMAX;
    int E = in_sizes[17] / 2;
    if (E > EMAX) E = EMAX;

    int nb_node = (N + 127) / 128;
    int nb_warp = (N * 32 + 255) / 256;
    int G = (N + 255) / 256;

    kinit<<<G, 256>>>((const int*)eidx, N);
    kconvert<<<(E + 255) / 256, 256>>>(eidx, E);
    kbsum<<<G, 256>>>(N);
    kbscan<<<1, 256>>>(G);
    kapply<<<G, 256>>>(N, E);
    kscatter<<<(E + 255) / 256, 256>>>(E);
    k1a<<<nb_node, 256>>>(x, wts, Wmlp, bmlp, Wgcn, Wgat, asrc, adst, Wr, bsage,
                          Wgin, bgin, out, N);
    kaggA<<<nb_warp, 256>>>(x, N);
    kaggB<<<nb_warp, 256>>>(N);
    kfin<<<nb_node, 256>>>(x, wts, Wl, Wgin, Wcheb, bcheb, bgcn, bgat, out, N);
}

// round 5
// speedup vs baseline: 1.2659x; 1.2659x over previous
#include <cuda_runtime.h>

#define NMAX 50000
#define EMAX 800000

// ---------------- scratch ----------------
__device__ __align__(16) int   g_ssrc[EMAX];
__device__ __align__(16) int   g_src[EMAX];
__device__ __align__(16) int   g_dst[EMAX];
__device__ __align__(16) int   g_hist[NMAX];
__device__ __align__(16) int   g_rowptr[NMAX + 1];
__device__ __align__(16) int   g_cnt[NMAX];
__device__ __align__(16) int   g_bsum[256];
__device__ __align__(16) int   g_boff[256];
__device__ int   g_is64;
__device__ __align__(16) float g_deg[NMAX];
__device__ __align__(16) float g_dinv[NMAX];
__device__ __align__(16) float g_dinvc[NMAX];
__device__ __align__(16) float g_el[NMAX];
__device__ __align__(16) float g_er[NMAX];
__device__ __align__(16) float g_m[NMAX];
__device__ __align__(16) float g_z[NMAX];
__device__ __align__(16) float g_nsum[NMAX * 64];
__device__ __align__(16) float g_xw[NMAX * 64];
__device__ __align__(16) float g_h[NMAX * 64];
__device__ __align__(16) float g_accsage[NMAX * 64];
__device__ __align__(16) float g_accgin[NMAX * 64];
__device__ __align__(16) float g_accgcn[NMAX * 64];
__device__ __align__(16) float g_t1[NMAX * 64];
__device__ __align__(16) float g_t2[NMAX * 64];
__device__ __align__(16) float g_accgat[NMAX * 64];

// ---------------- helpers ----------------
__device__ __forceinline__ float eluf(float v) { return v > 0.f ? v : expm1f(v); }
__device__ __forceinline__ float leakyf(float v) { return v > 0.f ? v : 0.2f * v; }

// load 64x64 fp32 matrix into smem (256 threads)
__device__ __forceinline__ void loadW(float* Wsm, const float* __restrict__ Wg, int t) {
    const float4* s = (const float4*)Wg;
    float4* d = (float4*)Wsm;
#pragma unroll
    for (int i = 0; i < 4; i++) d[t + i * 256] = s[t + i * 256];
}

__device__ __forceinline__ void gemv16(const float* __restrict__ Wsm,
                                       const float4* __restrict__ Xs,
                                       int tt, int jbase, float acc[16]) {
#pragma unroll 4
    for (int k4 = 0; k4 < 16; k4++) {
        float4 xq = Xs[k4 * 128 + tt];
        const float* wr = Wsm + (k4 * 4) * 64 + jbase;
#pragma unroll
        for (int s = 0; s < 4; s++) {
            float xv = (s == 0) ? xq.x : (s == 1) ? xq.y : (s == 2) ? xq.z : xq.w;
            const float4* wp = (const float4*)(wr + s * 64);
            float4 w0 = wp[0], w1 = wp[1], w2 = wp[2], w3 = wp[3];
            acc[0]  += xv * w0.x; acc[1]  += xv * w0.y; acc[2]  += xv * w0.z; acc[3]  += xv * w0.w;
            acc[4]  += xv * w1.x; acc[5]  += xv * w1.y; acc[6]  += xv * w1.z; acc[7]  += xv * w1.w;
            acc[8]  += xv * w2.x; acc[9]  += xv * w2.y; acc[10] += xv * w2.z; acc[11] += xv * w2.w;
            acc[12] += xv * w3.x; acc[13] += xv * w3.y; acc[14] += xv * w3.z; acc[15] += xv * w3.w;
        }
    }
}

__device__ __forceinline__ void loadXs(float4* Xs, const float4* __restrict__ row,
                                       int tt, int half) {
#pragma unroll
    for (int i = 0; i < 8; i++) {
        int k4 = half * 8 + i;
        Xs[k4 * 128 + tt] = row[k4];
    }
}

// ---------------- CSR build ----------------
__global__ void kinit(const int* __restrict__ raw, int N) {
    int i = blockIdx.x * blockDim.x + threadIdx.x;
    if (i < N) g_hist[i] = 0;
    if (i == 0) {
        int acc = 0;
        for (int k = 0; k < 64; k++) acc |= raw[2 * k + 1];
        g_is64 = (acc == 0) ? 1 : 0;
    }
}

__global__ void kconvert(const void* __restrict__ raw, int E) {
    int is64 = g_is64;
    for (int e = blockIdx.x * blockDim.x + threadIdx.x; e < E;
         e += gridDim.x * blockDim.x) {
        int s, d;
        if (is64) {
            const long long* p = (const long long*)raw;
            s = (int)p[e];
            d = (int)p[(size_t)E + e];
        } else {
            const int* p = (const int*)raw;
            s = p[e];
            d = p[E + e];
        }
        g_src[e] = s;
        g_dst[e] = d;
        atomicAdd(&g_hist[d], 1);
    }
}

__global__ __launch_bounds__(256) void kbsum(int N) {
    __shared__ int red[256];
    int t = threadIdx.x;
    int i = blockIdx.x * 256 + t;
    red[t] = (i < N) ? g_hist[i] : 0;
    __syncthreads();
    for (int o = 128; o; o >>= 1) {
        if (t < o) red[t] += red[t + o];
        __syncthreads();
    }
    if (t == 0) g_bsum[blockIdx.x] = red[0];
}

__global__ __launch_bounds__(256) void kbscan(int G) {
    __shared__ int s[256];
    int t = threadIdx.x;
    int v = (t < G) ? g_bsum[t] : 0;
    s[t] = v;
    __syncthreads();
    for (int o = 1; o < 256; o <<= 1) {
        int u = (t >= o) ? s[t - o] : 0;
        __syncthreads();
        s[t] += u;
        __syncthreads();
    }
    if (t < G) g_boff[t] = s[t] - v;
}

__global__ __launch_bounds__(256) void kapply(int N, int E) {
    __shared__ int wsum[8];
    int t = threadIdx.x;
    int lane = t & 31, wid = t >> 5;
    int i = blockIdx.x * 256 + t;
    int h = (i < N) ? g_hist[i] : 0;
    int val = h;
#pragma unroll
    for (int o = 1; o < 32; o <<= 1) {
        int u = __shfl_up_sync(0xffffffffu, val, o);
        if (lane >= o) val += u;
    }
    if (lane == 31) wsum[wid] = val;
    __syncthreads();
    if (t < 8) {
        int w = wsum[t];
#pragma unroll
        for (int o = 1; o < 8; o <<= 1) {
            int u = __shfl_up_sync(0xffu, w, o);
            if (t >= o) w += u;
        }
        wsum[t] = w;
    }
    __syncthreads();
    int excl = val - h + (wid ? wsum[wid - 1] : 0) + g_boff[blockIdx.x];
    if (i < N) {
        g_rowptr[i] = excl;
        g_cnt[i] = excl;
        float deg = (float)h;
        g_deg[i] = deg;
        g_dinv[i] = rsqrtf(deg + 1.f);
        g_dinvc[i] = rsqrtf(fmaxf(deg, 1.f));
    }
    if (i == 0) g_rowptr[N] = E;
}

__global__ void kscatter(int E) {
    int e = blockIdx.x * blockDim.x + threadIdx.x;
    if (e >= E) return;
    int d = g_dst[e];
    int pos = atomicAdd(&g_cnt[d], 1);
    g_ssrc[pos] = g_src[e];
}

// ---------------- node kernel 1a: all x-based GEMVs ----------------
__global__ __launch_bounds__(256) void k1a(
    const float* __restrict__ x, const float* __restrict__ wts,
    const float* __restrict__ Wmlp, const float* __restrict__ bmlp,
    const float* __restrict__ Wgcn,
    const float* __restrict__ Wgat, const float* __restrict__ asrc,
    const float* __restrict__ adst,
    const float* __restrict__ Wr, const float* __restrict__ bsage,
    const float* __restrict__ Wgin, const float* __restrict__ bgin,
    float* __restrict__ out, int N) {
    __shared__ __align__(16) float Wsm[4096];
    __shared__ float4 Xs[2048];
    __shared__ float els[128], ers[128];
    int t = threadIdx.x;
    int tt = t & 127, half = t >> 7;
    int node = blockIdx.x * 128 + tt;
    bool act = node < N;
    if (act) loadXs(Xs, (const float4*)(x + (size_t)node * 64), tt, half);
    // --- W_mlp ---
    loadW(Wsm, Wmlp, t);
    __syncthreads();
    if (act) {
        float w0 = wts[0];
        float4* o4 = (float4*)(out + (size_t)node * 64);
#pragma unroll
        for (int c = 0; c < 2; c++) {
            int cc = half * 2 + c;
            float acc[16];
#pragma unroll
            for (int j = 0; j < 16; j++) acc[j] = bmlp[cc * 16 + j];
            gemv16(Wsm, Xs, tt, cc * 16, acc);
#pragma unroll
            for (int j = 0; j < 4; j++)
                o4[cc * 4 + j] = make_float4(w0 * eluf(acc[4 * j + 0]),
                                             w0 * eluf(acc[4 * j + 1]),
                                             w0 * eluf(acc[4 * j + 2]),
                                             w0 * eluf(acc[4 * j + 3]));
        }
    }
    __syncthreads();
    // --- W_gcn ---
    loadW(Wsm, Wgcn, t);
    __syncthreads();
    if (act) {
        float4* o4 = (float4*)(g_xw + (size_t)node * 64);
#pragma unroll
        for (int c = 0; c < 2; c++) {
            int cc = half * 2 + c;
            float acc[16] = {};
            gemv16(Wsm, Xs, tt, cc * 16, acc);
#pragma unroll
            for (int j = 0; j < 4; j++)
                o4[cc * 4 + j] = make_float4(acc[4 * j], acc[4 * j + 1],
                                             acc[4 * j + 2], acc[4 * j + 3]);
        }
    }
    __syncthreads();
    // --- W_gat ---
    loadW(Wsm, Wgat, t);
    __syncthreads();
    {
        float el = 0.f, er = 0.f;
        if (act) {
            float4* o4 = (float4*)(g_h + (size_t)node * 64);
#pragma unroll
            for (int c = 0; c < 2; c++) {
                int cc = half * 2 + c;
                float acc[16] = {};
                gemv16(Wsm, Xs, tt, cc * 16, acc);
#pragma unroll
                for (int j = 0; j < 16; j++) {
                    el += acc[j] * asrc[cc * 16 + j];
                    er += acc[j] * adst[cc * 16 + j];
                }
#pragma unroll
                for (int j = 0; j < 4; j++)
                    o4[cc * 4 + j] = make_float4(acc[4 * j], acc[4 * j + 1],
                                                 acc[4 * j + 2], acc[4 * j + 3]);
            }
        }
        if (half == 1) { els[tt] = el; ers[tt] = er; }
        __syncthreads();
        if (half == 0 && act) {
            g_el[node] = el + els[tt];
            g_er[node] = er + ers[tt];
        }
    }
    __syncthreads();
    // --- Wr_sage ---
    loadW(Wsm, Wr, t);
    __syncthreads();
    if (act) {
        float4* o4 = (float4*)(g_accsage + (size_t)node * 64);
#pragma unroll
        for (int c = 0; c < 2; c++) {
            int cc = half * 2 + c;
            float acc[16];
#pragma unroll
            for (int j = 0; j < 16; j++) acc[j] = bsage[cc * 16 + j];
            gemv16(Wsm, Xs, tt, cc * 16, acc);
#pragma unroll
            for (int j = 0; j < 4; j++)
                o4[cc * 4 + j] = make_float4(acc[4 * j], acc[4 * j + 1],
                                             acc[4 * j + 2], acc[4 * j + 3]);
        }
    }
    __syncthreads();
    // --- W_gin ---
    loadW(Wsm, Wgin, t);
    __syncthreads();
    if (act) {
        float4* o4 = (float4*)(g_accgin + (size_t)node * 64);
#pragma unroll
        for (int c = 0; c < 2; c++) {
            int cc = half * 2 + c;
            float acc[16];
#pragma unroll
            for (int j = 0; j < 16; j++) acc[j] = bgin[cc * 16 + j];
            gemv16(Wsm, Xs, tt, cc * 16, acc);
#pragma unroll
            for (int j = 0; j < 4; j++)
                o4[cc * 4 + j] = make_float4(acc[4 * j], acc[4 * j + 1],
                                             acc[4 * j + 2], acc[4 * j + 3]);
        }
    }
}

// ---------------- gather pass A: nsum + gcn + T1 + full GAT softmax ---------
// one warp per destination node; lane covers 2 of the 64 features (R3 proven form)
__global__ __launch_bounds__(256) void kaggA(const float* __restrict__ x, int N) {
    int gw = (blockIdx.x * 256 + threadIdx.x) >> 5;
    if (gw >= N) return;
    int lane = threadIdx.x & 31;
    int d = gw;
    int beg = g_rowptr[d], end = g_rowptr[d + 1];
    float erd = g_er[d];
    float dinvd = g_dinv[d], dinvcd = g_dinvc[d];
    float es = leakyf(g_el[d] + erd);
    float m = es;
    for (int e = beg + lane; e < end; e += 32)
        m = fmaxf(m, leakyf(g_el[g_ssrc[e]] + erd));
#pragma unroll
    for (int o = 16; o; o >>= 1) m = fmaxf(m, __shfl_xor_sync(0xffffffffu, m, o));

    float ns0 = 0, ns1 = 0, gc0 = 0, gc1 = 0, t10 = 0, t11 = 0, ga0 = 0, ga1 = 0;
    float zacc = 0.f;
    for (int base = beg; base < end; base += 32) {
        int n = min(32, end - base);
        int sj = 0;
        float pj = 0.f, wgj = 0.f, wtj = 0.f;
        if (lane < n) {
            sj = g_ssrc[base + lane];
            pj = expf(leakyf(g_el[sj] + erd) - m);
            wgj = g_dinv[sj] * dinvd;
            wtj = g_dinvc[sj] * dinvcd;
            zacc += pj;
        }
        for (int j = 0; j < n; j++) {
            int s = __shfl_sync(0xffffffffu, sj, j);
            float p = __shfl_sync(0xffffffffu, pj, j);
            float wg = __shfl_sync(0xffffffffu, wgj, j);
            float wt = __shfl_sync(0xffffffffu, wtj, j);
            float2 xv  = ((const float2*)(x + (size_t)s * 64))[lane];
            float2 xwv = ((const float2*)(g_xw + (size_t)s * 64))[lane];
            float2 hv  = ((const float2*)(g_h + (size_t)s * 64))[lane];
            ns0 += xv.x;       ns1 += xv.y;
            t10 -= wt * xv.x;  t11 -= wt * xv.y;
            gc0 += wg * xwv.x; gc1 += wg * xwv.y;
            ga0 += p * hv.x;   ga1 += p * hv.y;
        }
    }
#pragma unroll
    for (int o = 16; o; o >>= 1) zacc += __shfl_xor_sync(0xffffffffu, zacc, o);
    float z = expf(es - m) + zacc;
    float invz = 1.f / (z + 1e-16f);
    ((float2*)(g_nsum   + (size_t)d * 64))[lane] = make_float2(ns0, ns1);
    ((float2*)(g_accgcn + (size_t)d * 64))[lane] = make_float2(gc0, gc1);
    ((float2*)(g_t1     + (size_t)d * 64))[lane] = make_float2(t10, t11);
    ((float2*)(g_accgat + (size_t)d * 64))[lane] = make_float2(ga0 * invz, ga1 * invz);
    if (lane == 0) { g_m[d] = m; g_z[d] = z; }
}

// ---------------- gather pass B: Cheb T2 acc = prop(T1) ----------------
__global__ __launch_bounds__(256) void kaggB(int N) {
    int gw = (blockIdx.x * 256 + threadIdx.x) >> 5;
    if (gw >= N) return;
    int lane = threadIdx.x & 31;
    int d = gw;
    int beg = g_rowptr[d], end = g_rowptr[d + 1];
    float dinvcd = g_dinvc[d];
    float t20 = 0.f, t21 = 0.f;
    for (int base = beg; base < end; base += 32) {
        int n = min(32, end - base);
        int sj = 0;
        float wtj = 0.f;
        if (lane < n) {
            sj = g_ssrc[base + lane];
            wtj = g_dinvc[sj] * dinvcd;
        }
        for (int j = 0; j < n; j++) {
            int s = __shfl_sync(0xffffffffu, sj, j);
            float wt = __shfl_sync(0xffffffffu, wtj, j);
            float2 v = ((const float2*)(g_t1 + (size_t)s * 64))[lane];
            t20 += wt * v.x;
            t21 += wt * v.y;
        }
    }
    ((float2*)(g_t2 + (size_t)d * 64))[lane] = make_float2(t20, t21);
}

// ---------------- fused final node kernel: sage + gin + cheb + gcn + gat ----
__global__ __launch_bounds__(256) void kfin(
    const float* __restrict__ x, const float* __restrict__ wts,
    const float* __restrict__ Wl, const float* __restrict__ Wgin,
    const float* __restrict__ Wcheb, const float* __restrict__ bcheb,
    const float* __restrict__ bgcn, const float* __restrict__ bgat,
    float* __restrict__ out, int N) {
    __shared__ __align__(16) float Wsm[4096];
    __shared__ float4 Xs[2048];
    int t = threadIdx.x;
    int tt = t & 127, half = t >> 7;
    int node = blockIdx.x * 128 + tt;
    bool act = node < N;
    float invd = 1.f;
    // phase 1: sage on nsum
    if (act) {
        loadXs(Xs, (const float4*)(g_nsum + (size_t)node * 64), tt, half);
        invd = 1.f / fmaxf(g_deg[node], 1.f);
    }
    loadW(Wsm, Wl, t);
    __syncthreads();
    if (act) {
        float w1 = wts[1];
        float4* o4 = (float4*)(out + (size_t)node * 64);
        const float4* as4 = (const float4*)(g_accsage + (size_t)node * 64);
#pragma unroll
        for (int c = 0; c < 2; c++) {
            int cc = half * 2 + c;
            float acc[16] = {};
            gemv16(Wsm, Xs, tt, cc * 16, acc);
#pragma unroll
            for (int j = 0; j < 4; j++) {
                float4 ov = o4[cc * 4 + j];
                float4 as = as4[cc * 4 + j];
                ov.x += w1 * eluf(acc[4 * j + 0] * invd + as.x);
                ov.y += w1 * eluf(acc[4 * j + 1] * invd + as.y);
                ov.z += w1 * eluf(acc[4 * j + 2] * invd + as.z);
                ov.w += w1 * eluf(acc[4 * j + 3] * invd + as.w);
                o4[cc * 4 + j] = ov;
            }
        }
    }
    __syncthreads();
    // phase 2: gin on nsum (Xs unchanged)
    loadW(Wsm, Wgin, t);
    __syncthreads();
    if (act) {
        float w5 = wts[5];
        float4* o4 = (float4*)(out + (size_t)node * 64);
        const float4* gi4 = (const float4*)(g_accgin + (size_t)node * 64);
#pragma unroll
        for (int c = 0; c < 2; c++) {
            int cc = half * 2 + c;
            float acc[16] = {};
            gemv16(Wsm, Xs, tt, cc * 16, acc);
#pragma unroll
            for (int j = 0; j < 4; j++) {
                float4 ov = o4[cc * 4 + j];
                float4 gi = gi4[cc * 4 + j];
                ov.x += w5 * eluf(acc[4 * j + 0] + gi.x);
                ov.y += w5 * eluf(acc[4 * j + 1] + gi.y);
                ov.z += w5 * eluf(acc[4 * j + 2] + gi.z);
                ov.w += w5 * eluf(acc[4 * j + 3] + gi.w);
                o4[cc * 4 + j] = ov;
            }
        }
    }
    __syncthreads();
    // phase 3: cheb T0 = x
    float cacc[32];
    if (act) loadXs(Xs, (const float4*)(x + (size_t)node * 64), tt, half);
    loadW(Wsm, Wcheb, t);
    __syncthreads();
    if (act) {
#pragma unroll
        for (int c = 0; c < 2; c++) {
            int cc = half * 2 + c;
            float acc[16];
#pragma unroll
            for (int j = 0; j < 16; j++) acc[j] = bcheb[cc * 16 + j];
            gemv16(Wsm, Xs, tt, cc * 16, acc);
#pragma unroll
            for (int j = 0; j < 16; j++) cacc[c * 16 + j] = acc[j];
        }
    }
    __syncthreads();
    // phase 4: cheb T1
    if (act) loadXs(Xs, (const float4*)(g_t1 + (size_t)node * 64), tt, half);
    loadW(Wsm, Wcheb + 4096, t);
    __syncthreads();
    if (act) {
#pragma unroll
        for (int c = 0; c < 2; c++) {
            int cc = half * 2 + c;
            float acc[16] = {};
            gemv16(Wsm, Xs, tt, cc * 16, acc);
#pragma unroll
            for (int j = 0; j < 16; j++) cacc[c * 16 + j] += acc[j];
        }
    }
    __syncthreads();
    // phase 5: cheb T2 = -2*prop(T1) - x, plus gcn/gat epilogue
    if (act) {
        const float4* xr = (const float4*)(x + (size_t)node * 64);
        const float4* t2r = (const float4*)(g_t2 + (size_t)node * 64);
#pragma unroll
        for (int i = 0; i < 8; i++) {
            int k4 = half * 8 + i;
            float4 a = xr[k4];
            float4 b = t2r[k4];
            Xs[k4 * 128 + tt] = make_float4(-2.f * b.x - a.x, -2.f * b.y - a.y,
                                            -2.f * b.z - a.z, -2.f * b.w - a.w);
        }
    }
    loadW(Wsm, Wcheb + 8192, t);
    __syncthreads();
    if (act) {
        float w2 = wts[2], w3 = wts[3], w4 = wts[4];
        float dinv = g_dinv[node];
        float di2 = dinv * dinv;
        float es = leakyf(g_el[node] + g_er[node]);
        float cs = expf(es - g_m[node]) / (g_z[node] + 1e-16f);
        const float4* gc4 = (const float4*)(g_accgcn + (size_t)node * 64);
        const float4* xw4 = (const float4*)(g_xw + (size_t)node * 64);
        const float4* ga4 = (const float4*)(g_accgat + (size_t)node * 64);
        const float4* h4 = (const float4*)(g_h + (size_t)node * 64);
        float4* o4 = (float4*)(out + (size_t)node * 64);
#pragma unroll
        for (int c = 0; c < 2; c++) {
            int cc = half * 2 + c;
            float acc[16] = {};
            gemv16(Wsm, Xs, tt, cc * 16, acc);
#pragma unroll
            for (int j = 0; j < 4; j++) {
                float4 gc = gc4[cc * 4 + j];
                float4 xwv = xw4[cc * 4 + j];
                float4 ga = ga4[cc * 4 + j];
                float4 hv = h4[cc * 4 + j];
                float4 bg = ((const float4*)bgcn)[cc * 4 + j];
                float4 bt = ((const float4*)bgat)[cc * 4 + j];
                float4 ov = o4[cc * 4 + j];
                ov.x += w2 * eluf(gc.x + xwv.x * di2 + bg.x)
                      + w3 * eluf(ga.x + cs * hv.x + bt.x)
                      + w4 * eluf(cacc[c * 16 + 4 * j + 0] + acc[4 * j + 0]);
                ov.y += w2 * eluf(gc.y + xwv.y * di2 + bg.y)
                      + w3 * eluf(ga.y + cs * hv.y + bt.y)
                      + w4 * eluf(cacc[c * 16 + 4 * j + 1] + acc[4 * j + 1]);
                ov.z += w2 * eluf(gc.z + xwv.z * di2 + bg.z)
                      + w3 * eluf(ga.z + cs * hv.z + bt.z)
                      + w4 * eluf(cacc[c * 16 + 4 * j + 2] + acc[4 * j + 2]);
                ov.w += w2 * eluf(gc.w + xwv.w * di2 + bg.w)
                      + w3 * eluf(ga.w + cs * hv.w + bt.w)
                      + w4 * eluf(cacc[c * 16 + 4 * j + 3] + acc[4 * j + 3]);
                o4[cc * 4 + j] = ov;
            }
        }
    }
}

// ---------------- host launcher ----------------
extern "C" void kernel_launch(void* const* d_in, const int* in_sizes, int n_in,
                              void* d_out, int out_size) {
    const float* x     = (const float*)d_in[0];
    const float* wts   = (const float*)d_in[1];
    const float* Wmlp  = (const float*)d_in[2];
    const float* bmlp  = (const float*)d_in[3];
    const float* Wl    = (const float*)d_in[4];
    const float* Wr    = (const float*)d_in[5];
    const float* bsage = (const float*)d_in[6];
    const float* Wgcn  = (const float*)d_in[7];
    const float* bgcn  = (const float*)d_in[8];
    const float* Wgat  = (const float*)d_in[9];
    const float* asrc  = (const float*)d_in[10];
    const float* adst  = (const float*)d_in[11];
    const float* bgat  = (const float*)d_in[12];
    const float* Wcheb = (const float*)d_in[13];
    const float* bcheb = (const float*)d_in[14];
    const float* Wgin  = (const float*)d_in[15];
    const float* bgin  = (const float*)d_in[16];
    const void*  eidx  = d_in[17];
    float* out = (float*)d_out;

    int N = in_sizes[0] / 64;
    if (N > NMAX) N = NMAX;
    int E = in_sizes[17] / 2;
    if (E > EMAX) E = EMAX;

    int nb_node = (N + 127) / 128;
    int nb_warp = (N * 32 + 255) / 256;
    int G = (N + 255) / 256;

    kinit<<<G, 256>>>((const int*)eidx, N);
    kconvert<<<(E + 255) / 256, 256>>>(eidx, E);
    kbsum<<<G, 256>>>(N);
    kbscan<<<1, 256>>>(G);
    kapply<<<G, 256>>>(N, E);
    kscatter<<<(E + 255) / 256, 256>>>(E);
    k1a<<<nb_node, 256>>>(x, wts, Wmlp, bmlp, Wgcn, Wgat, asrc, adst, Wr, bsage,
                          Wgin, bgin, out, N);
    kaggA<<<nb_warp, 256>>>(x, N);
    kaggB<<<nb_warp, 256>>>(N);
    kfin<<<nb_node, 256>>>(x, wts, Wl, Wgin, Wcheb, bcheb, bgcn, bgat, out, N);
}

// round 7
// speedup vs baseline: 1.5657x; 1.2369x over previous
#include <cuda_runtime.h>

#define NMAX 50000
#define EMAX 800000

// ---------------- scratch ----------------
__device__ __align__(16) int   g_ssrc[EMAX];
__device__ __align__(16) int   g_src[EMAX];
__device__ __align__(16) int   g_dst[EMAX];
__device__ __align__(16) int   g_hist[NMAX];
__device__ __align__(16) int   g_rowptr[NMAX + 1];
__device__ __align__(16) int   g_cnt[NMAX];
__device__ __align__(16) int   g_bsum[256];
__device__ __align__(16) int   g_boff[256];
__device__ int   g_is64;
__device__ __align__(16) float g_vsrc[64];
__device__ __align__(16) float g_vdst[64];
__device__ __align__(16) float g_deg[NMAX];
__device__ __align__(16) float g_dinv[NMAX];
__device__ __align__(16) float g_dinvc[NMAX];
__device__ __align__(16) float g_el[NMAX];
__device__ __align__(16) float g_er[NMAX];
__device__ __align__(16) float g_m[NMAX];
__device__ __align__(16) float g_z[NMAX];
__device__ __align__(16) float g_nsum[NMAX * 64];   // sum x[s]
__device__ __align__(16) float g_gcnx[NMAX * 64];   // sum wg*x[s]
__device__ __align__(16) float g_t1[NMAX * 64];     // -sum wt*x[s]
__device__ __align__(16) float g_t2[NMAX * 64];     // prop(T1)
__device__ __align__(16) float g_gatx[NMAX * 64];   // sum p*x[s] (unnormalized)
__device__ __align__(16) float g_accsage[NMAX * 64];

// ---------------- helpers ----------------
__device__ __forceinline__ float eluf(float v) { return v > 0.f ? v : expm1f(v); }
__device__ __forceinline__ float leakyf(float v) { return v > 0.f ? v : 0.2f * v; }

// load 64x64 fp32 matrix into smem (256 threads)
__device__ __forceinline__ void loadW(float* Wsm, const float* __restrict__ Wg, int t) {
    const float4* s = (const float4*)Wg;
    float4* d = (float4*)Wsm;
#pragma unroll
    for (int i = 0; i < 4; i++) d[t + i * 256] = s[t + i * 256];
}

__device__ __forceinline__ void gemv16(const float* __restrict__ Wsm,
                                       const float4* __restrict__ Xs,
                                       int tt, int jbase, float acc[16]) {
#pragma unroll 4
    for (int k4 = 0; k4 < 16; k4++) {
        float4 xq = Xs[k4 * 128 + tt];
        const float* wr = Wsm + (k4 * 4) * 64 + jbase;
#pragma unroll
        for (int s = 0; s < 4; s++) {
            float xv = (s == 0) ? xq.x : (s == 1) ? xq.y : (s == 2) ? xq.z : xq.w;
            const float4* wp = (const float4*)(wr + s * 64);
            float4 w0 = wp[0], w1 = wp[1], w2 = wp[2], w3 = wp[3];
            acc[0]  += xv * w0.x; acc[1]  += xv * w0.y; acc[2]  += xv * w0.z; acc[3]  += xv * w0.w;
            acc[4]  += xv * w1.x; acc[5]  += xv * w1.y; acc[6]  += xv * w1.z; acc[7]  += xv * w1.w;
            acc[8]  += xv * w2.x; acc[9]  += xv * w2.y; acc[10] += xv * w2.z; acc[11] += xv * w2.w;
            acc[12] += xv * w3.x; acc[13] += xv * w3.y; acc[14] += xv * w3.z; acc[15] += xv * w3.w;
        }
    }
}

__device__ __forceinline__ void loadXs(float4* Xs, const float4* __restrict__ row,
                                       int tt, int half) {
#pragma unroll
    for (int i = 0; i < 8; i++) {
        int k4 = half * 8 + i;
        Xs[k4 * 128 + tt] = row[k4];
    }
}

// ---------------- CSR build ----------------
__global__ void kinit(const int* __restrict__ raw, int N) {
    int i = blockIdx.x * blockDim.x + threadIdx.x;
    if (i < N) g_hist[i] = 0;
    if (i == 0) {
        int acc = 0;
        for (int k = 0; k < 64; k++) acc |= raw[2 * k + 1];
        g_is64 = (acc == 0) ? 1 : 0;
    }
}

__global__ void kconvert(const void* __restrict__ raw, int E) {
    int is64 = g_is64;
    for (int e = blockIdx.x * blockDim.x + threadIdx.x; e < E;
         e += gridDim.x * blockDim.x) {
        int s, d;
        if (is64) {
            const long long* p = (const long long*)raw;
            s = (int)p[e];
            d = (int)p[(size_t)E + e];
        } else {
            const int* p = (const int*)raw;
            s = p[e];
            d = p[E + e];
        }
        g_src[e] = s;
        g_dst[e] = d;
        atomicAdd(&g_hist[d], 1);
    }
}

// vsrc = Wgat @ a_src, vdst = Wgat @ a_dst (64 threads)
__global__ void kvec(const float* __restrict__ Wgat,
                     const float* __restrict__ asrc,
                     const float* __restrict__ adst) {
    int k = threadIdx.x;
    if (k < 64) {
        float s1 = 0.f, s2 = 0.f;
        const float* row = Wgat + k * 64;
        for (int j = 0; j < 64; j++) {
            float w = row[j];
            s1 += w * asrc[j];
            s2 += w * adst[j];
        }
        g_vsrc[k] = s1;
        g_vdst[k] = s2;
    }
}

__global__ __launch_bounds__(256) void kbsum(int N) {
    __shared__ int red[256];
    int t = threadIdx.x;
    int i = blockIdx.x * 256 + t;
    red[t] = (i < N) ? g_hist[i] : 0;
    __syncthreads();
    for (int o = 128; o; o >>= 1) {
        if (t < o) red[t] += red[t + o];
        __syncthreads();
    }
    if (t == 0) g_bsum[blockIdx.x] = red[0];
}

__global__ __launch_bounds__(256) void kbscan(int G) {
    __shared__ int s[256];
    int t = threadIdx.x;
    int v = (t < G) ? g_bsum[t] : 0;
    s[t] = v;
    __syncthreads();
    for (int o = 1; o < 256; o <<= 1) {
        int u = (t >= o) ? s[t - o] : 0;
        __syncthreads();
        s[t] += u;
        __syncthreads();
    }
    if (t < G) g_boff[t] = s[t] - v;
}

__global__ __launch_bounds__(256) void kapply(int N, int E) {
    __shared__ int wsum[8];
    int t = threadIdx.x;
    int lane = t & 31, wid = t >> 5;
    int i = blockIdx.x * 256 + t;
    int h = (i < N) ? g_hist[i] : 0;
    int val = h;
#pragma unroll
    for (int o = 1; o < 32; o <<= 1) {
        int u = __shfl_up_sync(0xffffffffu, val, o);
        if (lane >= o) val += u;
    }
    if (lane == 31) wsum[wid] = val;
    __syncthreads();
    if (t < 8) {
        int w = wsum[t];
#pragma unroll
        for (int o = 1; o < 8; o <<= 1) {
            int u = __shfl_up_sync(0xffu, w, o);
            if (t >= o) w += u;
        }
        wsum[t] = w;
    }
    __syncthreads();
    int excl = val - h + (wid ? wsum[wid - 1] : 0) + g_boff[blockIdx.x];
    if (i < N) {
        g_rowptr[i] = excl;
        g_cnt[i] = excl;
        float deg = (float)h;
        g_deg[i] = deg;
        g_dinv[i] = rsqrtf(deg + 1.f);
        g_dinvc[i] = rsqrtf(fmaxf(deg, 1.f));
    }
    if (i == 0) g_rowptr[N] = E;
}

__global__ void kscatter(int E) {
    int e = blockIdx.x * blockDim.x + threadIdx.x;
    if (e >= E) return;
    int d = g_dst[e];
    int pos = atomicAdd(&g_cnt[d], 1);
    g_ssrc[pos] = g_src[e];
}

// ---------------- node kernel 1a: mlp + sage-r GEMVs, el/er dots ------------
__global__ __launch_bounds__(256) void k1a(
    const float* __restrict__ x, const float* __restrict__ wts,
    const float* __restrict__ Wmlp, const float* __restrict__ bmlp,
    const float* __restrict__ Wr, const float* __restrict__ bsage,
    float* __restrict__ out, int N) {
    __shared__ __align__(16) float Wsm[4096];
    __shared__ float4 Xs[2048];
    __shared__ float vs[64], vd[64];
    __shared__ float els[128], ers[128];
    int t = threadIdx.x;
    int tt = t & 127, half = t >> 7;
    int node = blockIdx.x * 128 + tt;
    bool act = node < N;
    if (act) loadXs(Xs, (const float4*)(x + (size_t)node * 64), tt, half);
    if (t < 64) vs[t] = g_vsrc[t];
    else if (t < 128) vd[t - 64] = g_vdst[t - 64];
    loadW(Wsm, Wmlp, t);
    __syncthreads();
    // el/er partial dots over this thread's half of the row
    {
        float el = 0.f, er = 0.f;
        if (act) {
#pragma unroll
            for (int i = 0; i < 8; i++) {
                int k4 = half * 8 + i;
                float4 xq = Xs[k4 * 128 + tt];
                el += xq.x * vs[k4 * 4 + 0] + xq.y * vs[k4 * 4 + 1]
                    + xq.z * vs[k4 * 4 + 2] + xq.w * vs[k4 * 4 + 3];
                er += xq.x * vd[k4 * 4 + 0] + xq.y * vd[k4 * 4 + 1]
                    + xq.z * vd[k4 * 4 + 2] + xq.w * vd[k4 * 4 + 3];
            }
        }
        if (half == 1) { els[tt] = el; ers[tt] = er; }
        // --- W_mlp while waiting ---
        if (act) {
            float w0 = wts[0];
            float4* o4 = (float4*)(out + (size_t)node * 64);
#pragma unroll
            for (int c = 0; c < 2; c++) {
                int cc = half * 2 + c;
                float acc[16];
#pragma unroll
                for (int j = 0; j < 16; j++) acc[j] = bmlp[cc * 16 + j];
                gemv16(Wsm, Xs, tt, cc * 16, acc);
#pragma unroll
                for (int j = 0; j < 4; j++)
                    o4[cc * 4 + j] = make_float4(w0 * eluf(acc[4 * j + 0]),
                                                 w0 * eluf(acc[4 * j + 1]),
                                                 w0 * eluf(acc[4 * j + 2]),
                                                 w0 * eluf(acc[4 * j + 3]));
            }
        }
        __syncthreads();
        if (half == 0 && act) {
            g_el[node] = el + els[tt];
            g_er[node] = er + ers[tt];
        }
    }
    // --- Wr_sage: accsage = x@Wr + b_sage ---
    loadW(Wsm, Wr, t);
    __syncthreads();
    if (act) {
        float4* o4 = (float4*)(g_accsage + (size_t)node * 64);
#pragma unroll
        for (int c = 0; c < 2; c++) {
            int cc = half * 2 + c;
            float acc[16];
#pragma unroll
            for (int j = 0; j < 16; j++) acc[j] = bsage[cc * 16 + j];
            gemv16(Wsm, Xs, tt, cc * 16, acc);
#pragma unroll
            for (int j = 0; j < 4; j++)
                o4[cc * 4 + j] = make_float4(acc[4 * j], acc[4 * j + 1],
                                             acc[4 * j + 2], acc[4 * j + 3]);
        }
    }
}

// ---------------- gather pass A: 4 weighted sums of x rows -----------------
__global__ __launch_bounds__(256) void kaggA(const float* __restrict__ x, int N) {
    int gw = (blockIdx.x * 256 + threadIdx.x) >> 5;
    if (gw >= N) return;
    int lane = threadIdx.x & 31;
    int d = gw;
    int beg = g_rowptr[d], end = g_rowptr[d + 1];
    float erd = g_er[d];
    float dinvd = g_dinv[d], dinvcd = g_dinvc[d];
    float es = leakyf(g_el[d] + erd);
    float m = es;
    for (int e = beg + lane; e < end; e += 32)
        m = fmaxf(m, leakyf(g_el[g_ssrc[e]] + erd));
#pragma unroll
    for (int o = 16; o; o >>= 1) m = fmaxf(m, __shfl_xor_sync(0xffffffffu, m, o));

    float ns0 = 0, ns1 = 0, gc0 = 0, gc1 = 0, t10 = 0, t11 = 0, ga0 = 0, ga1 = 0;
    float zacc = 0.f;
    for (int base = beg; base < end; base += 32) {
        int n = min(32, end - base);
        int sj = 0;
        float pj = 0.f, wgj = 0.f, wtj = 0.f;
        if (lane < n) {
            sj = g_ssrc[base + lane];
            pj = expf(leakyf(g_el[sj] + erd) - m);
            wgj = g_dinv[sj] * dinvd;
            wtj = g_dinvc[sj] * dinvcd;
            zacc += pj;
        }
        for (int j = 0; j < n; j++) {
            int s = __shfl_sync(0xffffffffu, sj, j);
            float p = __shfl_sync(0xffffffffu, pj, j);
            float wg = __shfl_sync(0xffffffffu, wgj, j);
            float wt = __shfl_sync(0xffffffffu, wtj, j);
            float2 xv = ((const float2*)(x + (size_t)s * 64))[lane];
            ns0 += xv.x;       ns1 += xv.y;
            gc0 += wg * xv.x;  gc1 += wg * xv.y;
            t10 -= wt * xv.x;  t11 -= wt * xv.y;
            ga0 += p * xv.x;   ga1 += p * xv.y;
        }
    }
#pragma unroll
    for (int o = 16; o; o >>= 1) zacc += __shfl_xor_sync(0xffffffffu, zacc, o);
    float z = expf(es - m) + zacc;
    ((float2*)(g_nsum + (size_t)d * 64))[lane] = make_float2(ns0, ns1);
    ((float2*)(g_gcnx + (size_t)d * 64))[lane] = make_float2(gc0, gc1);
    ((float2*)(g_t1   + (size_t)d * 64))[lane] = make_float2(t10, t11);
    ((float2*)(g_gatx + (size_t)d * 64))[lane] = make_float2(ga0, ga1);
    if (lane == 0) { g_m[d] = m; g_z[d] = z; }
}

// ---------------- node kernel 1b: sage + gin finalize ----------------
__global__ __launch_bounds__(256) void k1b(const float* __restrict__ x,
                                           const float* __restrict__ wts,
                                           const float* __restrict__ Wl,
                                           const float* __restrict__ Wgin,
                                           const float* __restrict__ bgin,
                                           float* __restrict__ out, int N) {
    __shared__ __align__(16) float Wsm[4096];
    __shared__ float4 Xs[2048];
    int t = threadIdx.x;
    int tt = t & 127, half = t >> 7;
    int node = blockIdx.x * 128 + tt;
    bool act = node < N;
    float invd = 1.f;
    if (act) {
        loadXs(Xs, (const float4*)(g_nsum + (size_t)node * 64), tt, half);
        invd = 1.f / fmaxf(g_deg[node], 1.f);
    }
    loadW(Wsm, Wl, t);
    __syncthreads();
    if (act) {
        float w1 = wts[1];
        float4* o4 = (float4*)(out + (size_t)node * 64);
        const float4* as4 = (const float4*)(g_accsage + (size_t)node * 64);
#pragma unroll
        for (int c = 0; c < 2; c++) {
            int cc = half * 2 + c;
            float acc[16] = {};
            gemv16(Wsm, Xs, tt, cc * 16, acc);
#pragma unroll
            for (int j = 0; j < 4; j++) {
                float4 ov = o4[cc * 4 + j];
                float4 as = as4[cc * 4 + j];
                ov.x += w1 * eluf(acc[4 * j + 0] * invd + as.x);
                ov.y += w1 * eluf(acc[4 * j + 1] * invd + as.y);
                ov.z += w1 * eluf(acc[4 * j + 2] * invd + as.z);
                ov.w += w1 * eluf(acc[4 * j + 3] * invd + as.w);
                o4[cc * 4 + j] = ov;
            }
        }
    }
    __syncthreads();
    // Xs <- nsum + x for GIN
    if (act) {
        const float4* xr = (const float4*)(x + (size_t)node * 64);
#pragma unroll
        for (int i = 0; i < 8; i++) {
            int k4 = half * 8 + i;
            float4 v = Xs[k4 * 128 + tt];
            float4 a = xr[k4];
            Xs[k4 * 128 + tt] = make_float4(v.x + a.x, v.y + a.y, v.z + a.z, v.w + a.w);
        }
    }
    loadW(Wsm, Wgin, t);
    __syncthreads();
    if (act) {
        float w5 = wts[5];
        float4* o4 = (float4*)(out + (size_t)node * 64);
#pragma unroll
        for (int c = 0; c < 2; c++) {
            int cc = half * 2 + c;
            float acc[16];
#pragma unroll
            for (int j = 0; j < 16; j++) acc[j] = bgin[cc * 16 + j];
            gemv16(Wsm, Xs, tt, cc * 16, acc);
#pragma unroll
            for (int j = 0; j < 4; j++) {
                float4 ov = o4[cc * 4 + j];
                ov.x += w5 * eluf(acc[4 * j + 0]);
                ov.y += w5 * eluf(acc[4 * j + 1]);
                ov.z += w5 * eluf(acc[4 * j + 2]);
                ov.w += w5 * eluf(acc[4 * j + 3]);
                o4[cc * 4 + j] = ov;
            }
        }
    }
}

// ---------------- gather pass B: Cheb T2 acc = prop(T1) ----------------
__global__ __launch_bounds__(256) void kaggB(int N) {
    int gw = (blockIdx.x * 256 + threadIdx.x) >> 5;
    if (gw >= N) return;
    int lane = threadIdx.x & 31;
    int d = gw;
    int beg = g_rowptr[d], end = g_rowptr[d + 1];
    float dinvcd = g_dinvc[d];
    float t20 = 0.f, t21 = 0.f;
    for (int base = beg; base < end; base += 32) {
        int n = min(32, end - base);
        int sj = 0;
        float wtj = 0.f;
        if (lane < n) {
            sj = g_ssrc[base + lane];
            wtj = g_dinvc[sj] * dinvcd;
        }
        for (int j = 0; j < n; j++) {
            int s = __shfl_sync(0xffffffffu, sj, j);
            float wt = __shfl_sync(0xffffffffu, wtj, j);
            float2 v = ((const float2*)(g_t1 + (size_t)s * 64))[lane];
            t20 += wt * v.x;
            t21 += wt * v.y;
        }
    }
    ((float2*)(g_t2 + (size_t)d * 64))[lane] = make_float2(t20, t21);
}

// ---------------- final node kernel: cheb(3) + gcn + gat -------------------
__global__ __launch_bounds__(256) void kf(const float* __restrict__ x,
                                          const float* __restrict__ wts,
                                          const float* __restrict__ Wcheb,
                                          const float* __restrict__ bcheb,
                                          const float* __restrict__ Wgcn,
                                          const float* __restrict__ bgcn,
                                          const float* __restrict__ Wgat,
                                          const float* __restrict__ bgat,
                                          float* __restrict__ out, int N) {
    __shared__ __align__(16) float Wsm[4096];
    __shared__ float4 Xs[2048];
    int t = threadIdx.x;
    int tt = t & 127, half = t >> 7;
    int node = blockIdx.x * 128 + tt;
    bool act = node < N;
    float res[32];
    // phase 1: cheb T0 = x
    if (act) loadXs(Xs, (const float4*)(x + (size_t)node * 64), tt, half);
    loadW(Wsm, Wcheb, t);
    __syncthreads();
    if (act) {
#pragma unroll
        for (int c = 0; c < 2; c++) {
            int cc = half * 2 + c;
            float acc[16];
#pragma unroll
            for (int j = 0; j < 16; j++) acc[j] = bcheb[cc * 16 + j];
            gemv16(Wsm, Xs, tt, cc * 16, acc);
#pragma unroll
            for (int j = 0; j < 16; j++) res[c * 16 + j] = acc[j];
        }
    }
    __syncthreads();
    // phase 2: cheb T1
    if (act) loadXs(Xs, (const float4*)(g_t1 + (size_t)node * 64), tt, half);
    loadW(Wsm, Wcheb + 4096, t);
    __syncthreads();
    if (act) {
#pragma unroll
        for (int c = 0; c < 2; c++) {
            int cc = half * 2 + c;
            float acc[16] = {};
            gemv16(Wsm, Xs, tt, cc * 16, acc);
#pragma unroll
            for (int j = 0; j < 16; j++) res[c * 16 + j] += acc[j];
        }
    }
    __syncthreads();
    // phase 3: cheb T2 = -2*prop(T1) - x
    if (act) {
        const float4* xr = (const float4*)(x + (size_t)node * 64);
        const float4* t2r = (const float4*)(g_t2 + (size_t)node * 64);
#pragma unroll
        for (int i = 0; i < 8; i++) {
            int k4 = half * 8 + i;
            float4 a = xr[k4];
            float4 b = t2r[k4];
            Xs[k4 * 128 + tt] = make_float4(-2.f * b.x - a.x, -2.f * b.y - a.y,
                                            -2.f * b.z - a.z, -2.f * b.w - a.w);
        }
    }
    loadW(Wsm, Wcheb + 8192, t);
    __syncthreads();
    float w2 = wts[2], w3 = wts[3], w4 = wts[4];
    if (act) {
#pragma unroll
        for (int c = 0; c < 2; c++) {
            int cc = half * 2 + c;
            float acc[16] = {};
            gemv16(Wsm, Xs, tt, cc * 16, acc);
#pragma unroll
            for (int j = 0; j < 16; j++)
                res[c * 16 + j] = w4 * eluf(res[c * 16 + j] + acc[j]);
        }
    }
    __syncthreads();
    // phase 4: gcn: (gcnx + di2*x) @ Wgcn + bgcn
    if (act) {
        float dinv = g_dinv[node];
        float di2 = dinv * dinv;
        const float4* xr = (const float4*)(x + (size_t)node * 64);
        const float4* gr = (const float4*)(g_gcnx + (size_t)node * 64);
#pragma unroll
        for (int i = 0; i < 8; i++) {
            int k4 = half * 8 + i;
            float4 a = xr[k4];
            float4 g = gr[k4];
            Xs[k4 * 128 + tt] = make_float4(g.x + di2 * a.x, g.y + di2 * a.y,
                                            g.z + di2 * a.z, g.w + di2 * a.w);
        }
    }
    loadW(Wsm, Wgcn, t);
    __syncthreads();
    if (act) {
#pragma unroll
        for (int c = 0; c < 2; c++) {
            int cc = half * 2 + c;
            float acc[16];
#pragma unroll
            for (int j = 0; j < 16; j++) acc[j] = bgcn[cc * 16 + j];
            gemv16(Wsm, Xs, tt, cc * 16, acc);
#pragma unroll
            for (int j = 0; j < 16; j++) res[c * 16 + j] += w2 * eluf(acc[j]);
        }
    }
    __syncthreads();
    // phase 5: gat: invz*(gatx + cs*x) @ Wgat + bgat
    if (act) {
        float es = leakyf(g_el[node] + g_er[node]);
        float cs = expf(es - g_m[node]);
        float invz = 1.f / (g_z[node] + 1e-16f);
        const float4* xr = (const float4*)(x + (size_t)node * 64);
        const float4* gr = (const float4*)(g_gatx + (size_t)node * 64);
#pragma unroll
        for (int i = 0; i < 8; i++) {
            int k4 = half * 8 + i;
            float4 a = xr[k4];
            float4 g = gr[k4];
            Xs[k4 * 128 + tt] = make_float4(invz * (g.x + cs * a.x),
                                            invz * (g.y + cs * a.y),
                                            invz * (g.z + cs * a.z),
                                            invz * (g.w + cs * a.w));
        }
    }
    loadW(Wsm, Wgat, t);
    __syncthreads();
    if (act) {
        float4* o4 = (float4*)(out + (size_t)node * 64);
#pragma unroll
        for (int c = 0; c < 2; c++) {
            int cc = half * 2 + c;
            float acc[16];
#pragma unroll
            for (int j = 0; j < 16; j++) acc[j] = bgat[cc * 16 + j];
            gemv16(Wsm, Xs, tt, cc * 16, acc);
#pragma unroll
            for (int j = 0; j < 4; j++) {
                float4 ov = o4[cc * 4 + j];
                ov.x += res[c * 16 + 4 * j + 0] + w3 * eluf(acc[4 * j + 0]);
                ov.y += res[c * 16 + 4 * j + 1] + w3 * eluf(acc[4 * j + 1]);
                ov.z += res[c * 16 + 4 * j + 2] + w3 * eluf(acc[4 * j + 2]);
                ov.w += res[c * 16 + 4 * j + 3] + w3 * eluf(acc[4 * j + 3]);
                o4[cc * 4 + j] = ov;
            }
        }
    }
}

// ---------------- host launcher ----------------
extern "C" void kernel_launch(void* const* d_in, const int* in_sizes, int n_in,
                              void* d_out, int out_size) {
    const float* x     = (const float*)d_in[0];
    const float* wts   = (const float*)d_in[1];
    const float* Wmlp  = (const float*)d_in[2];
    const float* bmlp  = (const float*)d_in[3];
    const float* Wl    = (const float*)d_in[4];
    const float* Wr    = (const float*)d_in[5];
    const float* bsage = (const float*)d_in[6];
    const float* Wgcn  = (const float*)d_in[7];
    const float* bgcn  = (const float*)d_in[8];
    const float* Wgat  = (const float*)d_in[9];
    const float* asrc  = (const float*)d_in[10];
    const float* adst  = (const float*)d_in[11];
    const float* bgat  = (const float*)d_in[12];
    const float* Wcheb = (const float*)d_in[13];
    const float* bcheb = (const float*)d_in[14];
    const float* Wgin  = (const float*)d_in[15];
    const float* bgin  = (const float*)d_in[16];
    const void*  eidx  = d_in[17];
    float* out = (float*)d_out;

    int N = in_sizes[0] / 64;
    if (N > NMAX) N = NMAX;
    int E = in_sizes[17] / 2;
    if (E > EMAX) E = EMAX;

    int nb_node = (N + 127) / 128;
    int nb_warp = (N * 32 + 255) / 256;
    int G = (N + 255) / 256;

    kinit<<<G, 256>>>((const int*)eidx, N);
    kconvert<<<(E + 255) / 256, 256>>>(eidx, E);
    kvec<<<1, 64>>>(Wgat, asrc, adst);
    kbsum<<<G, 256>>>(N);
    kbscan<<<1, 256>>>(G);
    kapply<<<G, 256>>>(N, E);
    kscatter<<<(E + 255) / 256, 256>>>(E);
    k1a<<<nb_node, 256>>>(x, wts, Wmlp, bmlp, Wr, bsage, out, N);
    kaggA<<<nb_warp, 256>>>(x, N);
    k1b<<<nb_node, 256>>>(x, wts, Wl, Wgin, bgin, out, N);
    kaggB<<<nb_warp, 256>>>(N);
    kf<<<nb_node, 256>>>(x, wts, Wcheb, bcheb, Wgcn, bgcn, Wgat, bgat, out, N);
}

// round 8
// speedup vs baseline: 1.7201x; 1.0986x over previous
#include <cuda_runtime.h>

#define NMAX 50000
#define EMAX 800000

// ---------------- scratch ----------------
__device__ __align__(16) int   g_ssrc[EMAX];
__device__ __align__(16) int   g_src[EMAX];
__device__ __align__(16) int   g_dst[EMAX];
__device__ __align__(16) int   g_hist[NMAX];
__device__ __align__(16) int   g_rowptr[NMAX + 1];
__device__ __align__(16) int   g_cnt[NMAX];
__device__ __align__(16) int   g_bsum[256];
__device__ __align__(16) int   g_boff[256];
__device__ int   g_is64;
__device__ __align__(16) float g_vsrc[64];
__device__ __align__(16) float g_vdst[64];
__device__ __align__(16) float g_deg[NMAX];
__device__ __align__(16) float g_dinv[NMAX];
__device__ __align__(16) float g_dinvc[NMAX];
__device__ __align__(16) float g_el[NMAX];
__device__ __align__(16) float g_er[NMAX];
__device__ __align__(16) float g_m[NMAX];
__device__ __align__(16) float g_z[NMAX];
__device__ __align__(16) float g_nsum[NMAX * 64];
__device__ __align__(16) float g_gcnx[NMAX * 64];
__device__ __align__(16) float g_t1[NMAX * 64];
__device__ __align__(16) float g_t2[NMAX * 64];
__device__ __align__(16) float g_gatx[NMAX * 64];
__device__ __align__(16) float g_accsage[NMAX * 64];

// ---------------- helpers ----------------
__device__ __forceinline__ float eluf(float v) { return v > 0.f ? v : expm1f(v); }
__device__ __forceinline__ float leakyf(float v) { return v > 0.f ? v : 0.2f * v; }

__device__ __forceinline__ unsigned long long pack2(float lo, float hi) {
    unsigned long long r;
    asm("mov.b64 %0, {%1, %2};" : "=l"(r) : "f"(lo), "f"(hi));
    return r;
}
__device__ __forceinline__ float2 unpack2(unsigned long long v) {
    float lo, hi;
    asm("mov.b64 {%0, %1}, %2;" : "=f"(lo), "=f"(hi) : "l"(v));
    return make_float2(lo, hi);
}
#define FMA2(acc, w, xx) \
    asm("fma.rn.f32x2 %0, %1, %2, %0;" : "+l"(acc) : "l"(w), "l"(xx))

// load 64x64 fp32 matrix into smem (256 threads)
__device__ __forceinline__ void loadW(float* Wsm, const float* __restrict__ Wg, int t) {
    const float4* s = (const float4*)Wg;
    float4* d = (float4*)Wsm;
#pragma unroll
    for (int i = 0; i < 4; i++) d[t + i * 256] = s[t + i * 256];
}

// acc2[8] (packed f32x2 pairs) += sum_k xrow[k] * W[k][jbase + 2j..2j+1]
__device__ __forceinline__ void gemv16x2(const float* __restrict__ Wsm,
                                         const float4* __restrict__ Xs,
                                         int tt, int jbase,
                                         unsigned long long acc2[8]) {
#pragma unroll 4
    for (int k4 = 0; k4 < 16; k4++) {
        float4 xq = Xs[k4 * 128 + tt];
#pragma unroll
        for (int s = 0; s < 4; s++) {
            float xv = (s == 0) ? xq.x : (s == 1) ? xq.y : (s == 2) ? xq.z : xq.w;
            unsigned long long xx = pack2(xv, xv);
            const ulonglong2* wp = (const ulonglong2*)(Wsm + (k4 * 4 + s) * 64 + jbase);
            ulonglong2 a = wp[0], b = wp[1], c = wp[2], d = wp[3];
            FMA2(acc2[0], a.x, xx); FMA2(acc2[1], a.y, xx);
            FMA2(acc2[2], b.x, xx); FMA2(acc2[3], b.y, xx);
            FMA2(acc2[4], c.x, xx); FMA2(acc2[5], c.y, xx);
            FMA2(acc2[6], d.x, xx); FMA2(acc2[7], d.y, xx);
        }
    }
}

__device__ __forceinline__ void accInitBias(unsigned long long a[8],
                                            const float* __restrict__ b) {
#pragma unroll
    for (int j = 0; j < 8; j++) a[j] = pack2(b[2 * j], b[2 * j + 1]);
}
__device__ __forceinline__ void accInitZero(unsigned long long a[8]) {
#pragma unroll
    for (int j = 0; j < 8; j++) a[j] = 0ull;
}
__device__ __forceinline__ void accOut(const unsigned long long a[8], float o[16]) {
#pragma unroll
    for (int j = 0; j < 8; j++) {
        float2 p = unpack2(a[j]);
        o[2 * j] = p.x;
        o[2 * j + 1] = p.y;
    }
}

__device__ __forceinline__ void loadXs(float4* Xs, const float4* __restrict__ row,
                                       int tt, int half) {
#pragma unroll
    for (int i = 0; i < 8; i++) {
        int k4 = half * 8 + i;
        Xs[k4 * 128 + tt] = row[k4];
    }
}

// ---------------- CSR build ----------------
__global__ void kinit(const int* __restrict__ raw, int N) {
    int i = blockIdx.x * blockDim.x + threadIdx.x;
    if (i < N) g_hist[i] = 0;
    if (i == 0) {
        int acc = 0;
        for (int k = 0; k < 64; k++) acc |= raw[2 * k + 1];
        g_is64 = (acc == 0) ? 1 : 0;
    }
}

__global__ void kconvert(const void* __restrict__ raw, int E) {
    int is64 = g_is64;
    for (int e = blockIdx.x * blockDim.x + threadIdx.x; e < E;
         e += gridDim.x * blockDim.x) {
        int s, d;
        if (is64) {
            const long long* p = (const long long*)raw;
            s = (int)p[e];
            d = (int)p[(size_t)E + e];
        } else {
            const int* p = (const int*)raw;
            s = p[e];
            d = p[E + e];
        }
        g_src[e] = s;
        g_dst[e] = d;
        atomicAdd(&g_hist[d], 1);
    }
}

__global__ void kvec(const float* __restrict__ Wgat,
                     const float* __restrict__ asrc,
                     const float* __restrict__ adst) {
    int k = threadIdx.x;
    if (k < 64) {
        float s1 = 0.f, s2 = 0.f;
        const float* row = Wgat + k * 64;
        for (int j = 0; j < 64; j++) {
            float w = row[j];
            s1 += w * asrc[j];
            s2 += w * adst[j];
        }
        g_vsrc[k] = s1;
        g_vdst[k] = s2;
    }
}

__global__ __launch_bounds__(256) void kbsum(int N) {
    __shared__ int red[256];
    int t = threadIdx.x;
    int i = blockIdx.x * 256 + t;
    red[t] = (i < N) ? g_hist[i] : 0;
    __syncthreads();
    for (int o = 128; o; o >>= 1) {
        if (t < o) red[t] += red[t + o];
        __syncthreads();
    }
    if (t == 0) g_bsum[blockIdx.x] = red[0];
}

__global__ __launch_bounds__(256) void kbscan(int G) {
    __shared__ int s[256];
    int t = threadIdx.x;
    int v = (t < G) ? g_bsum[t] : 0;
    s[t] = v;
    __syncthreads();
    for (int o = 1; o < 256; o <<= 1) {
        int u = (t >= o) ? s[t - o] : 0;
        __syncthreads();
        s[t] += u;
        __syncthreads();
    }
    if (t < G) g_boff[t] = s[t] - v;
}

__global__ __launch_bounds__(256) void kapply(int N, int E) {
    __shared__ int wsum[8];
    int t = threadIdx.x;
    int lane = t & 31, wid = t >> 5;
    int i = blockIdx.x * 256 + t;
    int h = (i < N) ? g_hist[i] : 0;
    int val = h;
#pragma unroll
    for (int o = 1; o < 32; o <<= 1) {
        int u = __shfl_up_sync(0xffffffffu, val, o);
        if (lane >= o) val += u;
    }
    if (lane == 31) wsum[wid] = val;
    __syncthreads();
    if (t < 8) {
        int w = wsum[t];
#pragma unroll
        for (int o = 1; o < 8; o <<= 1) {
            int u = __shfl_up_sync(0xffu, w, o);
            if (t >= o) w += u;
        }
        wsum[t] = w;
    }
    __syncthreads();
    int excl = val - h + (wid ? wsum[wid - 1] : 0) + g_boff[blockIdx.x];
    if (i < N) {
        g_rowptr[i] = excl;
        g_cnt[i] = excl;
        float deg = (float)h;
        g_deg[i] = deg;
        g_dinv[i] = rsqrtf(deg + 1.f);
        g_dinvc[i] = rsqrtf(fmaxf(deg, 1.f));
    }
    if (i == 0) g_rowptr[N] = E;
}

__global__ void kscatter(int E) {
    int e = blockIdx.x * blockDim.x + threadIdx.x;
    if (e >= E) return;
    int d = g_dst[e];
    int pos = atomicAdd(&g_cnt[d], 1);
    g_ssrc[pos] = g_src[e];
}

// ---------------- node kernel 1a: mlp + sage-r GEMVs, el/er dots ------------
__global__ __launch_bounds__(256) void k1a(
    const float* __restrict__ x, const float* __restrict__ wts,
    const float* __restrict__ Wmlp, const float* __restrict__ bmlp,
    const float* __restrict__ Wr, const float* __restrict__ bsage,
    float* __restrict__ out, int N) {
    __shared__ __align__(16) float Wsm[4096];
    __shared__ float4 Xs[2048];
    __shared__ float vs[64], vd[64];
    __shared__ float els[128], ers[128];
    int t = threadIdx.x;
    int tt = t & 127, half = t >> 7;
    int node = blockIdx.x * 128 + tt;
    bool act = node < N;
    if (act) loadXs(Xs, (const float4*)(x + (size_t)node * 64), tt, half);
    if (t < 64) vs[t] = g_vsrc[t];
    else if (t < 128) vd[t - 64] = g_vdst[t - 64];
    loadW(Wsm, Wmlp, t);
    __syncthreads();
    {
        float el = 0.f, er = 0.f;
        if (act) {
#pragma unroll
            for (int i = 0; i < 8; i++) {
                int k4 = half * 8 + i;
                float4 xq = Xs[k4 * 128 + tt];
                el += xq.x * vs[k4 * 4 + 0] + xq.y * vs[k4 * 4 + 1]
                    + xq.z * vs[k4 * 4 + 2] + xq.w * vs[k4 * 4 + 3];
                er += xq.x * vd[k4 * 4 + 0] + xq.y * vd[k4 * 4 + 1]
                    + xq.z * vd[k4 * 4 + 2] + xq.w * vd[k4 * 4 + 3];
            }
        }
        if (half == 1) { els[tt] = el; ers[tt] = er; }
        if (act) {
            float w0 = wts[0];
            float4* o4 = (float4*)(out + (size_t)node * 64);
#pragma unroll
            for (int c = 0; c < 2; c++) {
                int cc = half * 2 + c;
                unsigned long long a2[8];
                accInitBias(a2, bmlp + cc * 16);
                gemv16x2(Wsm, Xs, tt, cc * 16, a2);
                float acc[16];
                accOut(a2, acc);
#pragma unroll
                for (int j = 0; j < 4; j++)
                    o4[cc * 4 + j] = make_float4(w0 * eluf(acc[4 * j + 0]),
                                                 w0 * eluf(acc[4 * j + 1]),
                                                 w0 * eluf(acc[4 * j + 2]),
                                                 w0 * eluf(acc[4 * j + 3]));
            }
        }
        __syncthreads();
        if (half == 0 && act) {
            g_el[node] = el + els[tt];
            g_er[node] = er + ers[tt];
        }
    }
    loadW(Wsm, Wr, t);
    __syncthreads();
    if (act) {
        float4* o4 = (float4*)(g_accsage + (size_t)node * 64);
#pragma unroll
        for (int c = 0; c < 2; c++) {
            int cc = half * 2 + c;
            unsigned long long a2[8];
            accInitBias(a2, bsage + cc * 16);
            gemv16x2(Wsm, Xs, tt, cc * 16, a2);
            float acc[16];
            accOut(a2, acc);
#pragma unroll
            for (int j = 0; j < 4; j++)
                o4[cc * 4 + j] = make_float4(acc[4 * j], acc[4 * j + 1],
                                             acc[4 * j + 2], acc[4 * j + 3]);
        }
    }
}

// ---------------- gather pass A: 4 weighted sums of x rows -----------------
__global__ __launch_bounds__(256) void kaggA(const float* __restrict__ x, int N) {
    int gw = (blockIdx.x * 256 + threadIdx.x) >> 5;
    if (gw >= N) return;
    int lane = threadIdx.x & 31;
    int d = gw;
    int beg = g_rowptr[d], end = g_rowptr[d + 1];
    float erd = g_er[d];
    float dinvd = g_dinv[d], dinvcd = g_dinvc[d];
    float es = leakyf(g_el[d] + erd);
    float m = es;
    for (int e = beg + lane; e < end; e += 32)
        m = fmaxf(m, leakyf(g_el[g_ssrc[e]] + erd));
#pragma unroll
    for (int o = 16; o; o >>= 1) m = fmaxf(m, __shfl_xor_sync(0xffffffffu, m, o));

    float ns0 = 0, ns1 = 0, gc0 = 0, gc1 = 0, t10 = 0, t11 = 0, ga0 = 0, ga1 = 0;
    float zacc = 0.f;
    for (int base = beg; base < end; base += 32) {
        int n = min(32, end - base);
        int sj = 0;
        float pj = 0.f, wgj = 0.f, wtj = 0.f;
        if (lane < n) {
            sj = g_ssrc[base + lane];
            pj = expf(leakyf(g_el[sj] + erd) - m);
            wgj = g_dinv[sj] * dinvd;
            wtj = g_dinvc[sj] * dinvcd;
            zacc += pj;
        }
        for (int j = 0; j < n; j++) {
            int s = __shfl_sync(0xffffffffu, sj, j);
            float p = __shfl_sync(0xffffffffu, pj, j);
            float wg = __shfl_sync(0xffffffffu, wgj, j);
            float wt = __shfl_sync(0xffffffffu, wtj, j);
            float2 xv = ((const float2*)(x + (size_t)s * 64))[lane];
            ns0 += xv.x;       ns1 += xv.y;
            gc0 += wg * xv.x;  gc1 += wg * xv.y;
            t10 -= wt * xv.x;  t11 -= wt * xv.y;
            ga0 += p * xv.x;   ga1 += p * xv.y;
        }
    }
#pragma unroll
    for (int o = 16; o; o >>= 1) zacc += __shfl_xor_sync(0xffffffffu, zacc, o);
    float z = expf(es - m) + zacc;
    ((float2*)(g_nsum + (size_t)d * 64))[lane] = make_float2(ns0, ns1);
    ((float2*)(g_gcnx + (size_t)d * 64))[lane] = make_float2(gc0, gc1);
    ((float2*)(g_t1   + (size_t)d * 64))[lane] = make_float2(t10, t11);
    ((float2*)(g_gatx + (size_t)d * 64))[lane] = make_float2(ga0, ga1);
    if (lane == 0) { g_m[d] = m; g_z[d] = z; }
}

// ---------------- node kernel 1b: sage + gin finalize ----------------
__global__ __launch_bounds__(256) void k1b(const float* __restrict__ x,
                                           const float* __restrict__ wts,
                                           const float* __restrict__ Wl,
                                           const float* __restrict__ Wgin,
                                           const float* __restrict__ bgin,
                                           float* __restrict__ out, int N) {
    __shared__ __align__(16) float Wsm[4096];
    __shared__ float4 Xs[2048];
    int t = threadIdx.x;
    int tt = t & 127, half = t >> 7;
    int node = blockIdx.x * 128 + tt;
    bool act = node < N;
    float invd = 1.f;
    if (act) {
        loadXs(Xs, (const float4*)(g_nsum + (size_t)node * 64), tt, half);
        invd = 1.f / fmaxf(g_deg[node], 1.f);
    }
    loadW(Wsm, Wl, t);
    __syncthreads();
    if (act) {
        float w1 = wts[1];
        float4* o4 = (float4*)(out + (size_t)node * 64);
        const float4* as4 = (const float4*)(g_accsage + (size_t)node * 64);
#pragma unroll
        for (int c = 0; c < 2; c++) {
            int cc = half * 2 + c;
            unsigned long long a2[8];
            accInitZero(a2);
            gemv16x2(Wsm, Xs, tt, cc * 16, a2);
            float acc[16];
            accOut(a2, acc);
#pragma unroll
            for (int j = 0; j < 4; j++) {
                float4 ov = o4[cc * 4 + j];
                float4 as = as4[cc * 4 + j];
                ov.x += w1 * eluf(acc[4 * j + 0] * invd + as.x);
                ov.y += w1 * eluf(acc[4 * j + 1] * invd + as.y);
                ov.z += w1 * eluf(acc[4 * j + 2] * invd + as.z);
                ov.w += w1 * eluf(acc[4 * j + 3] * invd + as.w);
                o4[cc * 4 + j] = ov;
            }
        }
    }
    __syncthreads();
    if (act) {
        const float4* xr = (const float4*)(x + (size_t)node * 64);
#pragma unroll
        for (int i = 0; i < 8; i++) {
            int k4 = half * 8 + i;
            float4 v = Xs[k4 * 128 + tt];
            float4 a = xr[k4];
            Xs[k4 * 128 + tt] = make_float4(v.x + a.x, v.y + a.y, v.z + a.z, v.w + a.w);
        }
    }
    loadW(Wsm, Wgin, t);
    __syncthreads();
    if (act) {
        float w5 = wts[5];
        float4* o4 = (float4*)(out + (size_t)node * 64);
#pragma unroll
        for (int c = 0; c < 2; c++) {
            int cc = half * 2 + c;
            unsigned long long a2[8];
            accInitBias(a2, bgin + cc * 16);
            gemv16x2(Wsm, Xs, tt, cc * 16, a2);
            float acc[16];
            accOut(a2, acc);
#pragma unroll
            for (int j = 0; j < 4; j++) {
                float4 ov = o4[cc * 4 + j];
                ov.x += w5 * eluf(acc[4 * j + 0]);
                ov.y += w5 * eluf(acc[4 * j + 1]);
                ov.z += w5 * eluf(acc[4 * j + 2]);
                ov.w += w5 * eluf(acc[4 * j + 3]);
                o4[cc * 4 + j] = ov;
            }
        }
    }
}

// ---------------- gather pass B: Cheb T2 acc = prop(T1) ----------------
__global__ __launch_bounds__(256) void kaggB(int N) {
    int gw = (blockIdx.x * 256 + threadIdx.x) >> 5;
    if (gw >= N) return;
    int lane = threadIdx.x & 31;
    int d = gw;
    int beg = g_rowptr[d], end = g_rowptr[d + 1];
    float dinvcd = g_dinvc[d];
    float t20 = 0.f, t21 = 0.f;
    for (int base = beg; base < end; base += 32) {
        int n = min(32, end - base);
        int sj = 0;
        float wtj = 0.f;
        if (lane < n) {
            sj = g_ssrc[base + lane];
            wtj = g_dinvc[sj] * dinvcd;
        }
        for (int j = 0; j < n; j++) {
            int s = __shfl_sync(0xffffffffu, sj, j);
            float wt = __shfl_sync(0xffffffffu, wtj, j);
            float2 v = ((const float2*)(g_t1 + (size_t)s * 64))[lane];
            t20 += wt * v.x;
            t21 += wt * v.y;
        }
    }
    ((float2*)(g_t2 + (size_t)d * 64))[lane] = make_float2(t20, t21);
}

// ---------------- final node kernel: cheb(3) + gcn + gat -------------------
__global__ __launch_bounds__(256) void kf(const float* __restrict__ x,
                                          const float* __restrict__ wts,
                                          const float* __restrict__ Wcheb,
                                          const float* __restrict__ bcheb,
                                          const float* __restrict__ Wgcn,
                                          const float* __restrict__ bgcn,
                                          const float* __restrict__ Wgat,
                                          const float* __restrict__ bgat,
                                          float* __restrict__ out, int N) {
    __shared__ __align__(16) float Wsm[4096];
    __shared__ float4 Xs[2048];
    int t = threadIdx.x;
    int tt = t & 127, half = t >> 7;
    int node = blockIdx.x * 128 + tt;
    bool act = node < N;
    float res[32];
    // phase 1: cheb T0 = x
    if (act) loadXs(Xs, (const float4*)(x + (size_t)node * 64), tt, half);
    loadW(Wsm, Wcheb, t);
    __syncthreads();
    if (act) {
#pragma unroll
        for (int c = 0; c < 2; c++) {
            int cc = half * 2 + c;
            unsigned long long a2[8];
            accInitBias(a2, bcheb + cc * 16);
            gemv16x2(Wsm, Xs, tt, cc * 16, a2);
            accOut(a2, res + c * 16);
        }
    }
    __syncthreads();
    // phase 2: cheb T1
    if (act) loadXs(Xs, (const float4*)(g_t1 + (size_t)node * 64), tt, half);
    loadW(Wsm, Wcheb + 4096, t);
    __syncthreads();
    if (act) {
#pragma unroll
        for (int c = 0; c < 2; c++) {
            int cc = half * 2 + c;
            unsigned long long a2[8];
            accInitZero(a2);
            gemv16x2(Wsm, Xs, tt, cc * 16, a2);
            float acc[16];
            accOut(a2, acc);
#pragma unroll
            for (int j = 0; j < 16; j++) res[c * 16 + j] += acc[j];
        }
    }
    __syncthreads();
    // phase 3: cheb T2 = -2*prop(T1) - x
    if (act) {
        const float4* xr = (const float4*)(x + (size_t)node * 64);
        const float4* t2r = (const float4*)(g_t2 + (size_t)node * 64);
#pragma unroll
        for (int i = 0; i < 8; i++) {
            int k4 = half * 8 + i;
            float4 a = xr[k4];
            float4 b = t2r[k4];
            Xs[k4 * 128 + tt] = make_float4(-2.f * b.x - a.x, -2.f * b.y - a.y,
                                            -2.f * b.z - a.z, -2.f * b.w - a.w);
        }
    }
    loadW(Wsm, Wcheb + 8192, t);
    __syncthreads();
    float w2 = wts[2], w3 = wts[3], w4 = wts[4];
    if (act) {
#pragma unroll
        for (int c = 0; c < 2; c++) {
            int cc = half * 2 + c;
            unsigned long long a2[8];
            accInitZero(a2);
            gemv16x2(Wsm, Xs, tt, cc * 16, a2);
            float acc[16];
            accOut(a2, acc);
#pragma unroll
            for (int j = 0; j < 16; j++)
                res[c * 16 + j] = w4 * eluf(res[c * 16 + j] + acc[j]);
        }
    }
    __syncthreads();
    // phase 4: gcn: (gcnx + di2*x) @ Wgcn + bgcn
    if (act) {
        float dinv = g_dinv[node];
        float di2 = dinv * dinv;
        const float4* xr = (const float4*)(x + (size_t)node * 64);
        const float4* gr = (const float4*)(g_gcnx + (size_t)node * 64);
#pragma unroll
        for (int i = 0; i < 8; i++) {
            int k4 = half * 8 + i;
            float4 a = xr[k4];
            float4 g = gr[k4];
            Xs[k4 * 128 + tt] = make_float4(g.x + di2 * a.x, g.y + di2 * a.y,
                                            g.z + di2 * a.z, g.w + di2 * a.w);
        }
    }
    loadW(Wsm, Wgcn, t);
    __syncthreads();
    if (act) {
#pragma unroll
        for (int c = 0; c < 2; c++) {
            int cc = half * 2 + c;
            unsigned long long a2[8];
            accInitBias(a2, bgcn + cc * 16);
            gemv16x2(Wsm, Xs, tt, cc * 16, a2);
            float acc[16];
            accOut(a2, acc);
#pragma unroll
            for (int j = 0; j < 16; j++) res[c * 16 + j] += w2 * eluf(acc[j]);
        }
    }
    __syncthreads();
    // phase 5: gat: invz*(gatx + cs*x) @ Wgat + bgat
    if (act) {
        float es = leakyf(g_el[node] + g_er[node]);
        float cs = expf(es - g_m[node]);
        float invz = 1.f / (g_z[node] + 1e-16f);
        const float4* xr = (const float4*)(x + (size_t)node * 64);
        const float4* gr = (const float4*)(g_gatx + (size_t)node * 64);
#pragma unroll
        for (int i = 0; i < 8; i++) {
            int k4 = half * 8 + i;
            float4 a = xr[k4];
            float4 g = gr[k4];
            Xs[k4 * 128 + tt] = make_float4(invz * (g.x + cs * a.x),
                                            invz * (g.y + cs * a.y),
                                            invz * (g.z + cs * a.z),
                                            invz * (g.w + cs * a.w));
        }
    }
    loadW(Wsm, Wgat, t);
    __syncthreads();
    if (act) {
        float4* o4 = (float4*)(out + (size_t)node * 64);
#pragma unroll
        for (int c = 0; c < 2; c++) {
            int cc = half * 2 + c;
            unsigned long long a2[8];
            accInitBias(a2, bgat + cc * 16);
            gemv16x2(Wsm, Xs, tt, cc * 16, a2);
            float acc[16];
            accOut(a2, acc);
#pragma unroll
            for (int j = 0; j < 4; j++) {
                float4 ov = o4[cc * 4 + j];
                ov.x += res[c * 16 + 4 * j + 0] + w3 * eluf(acc[4 * j + 0]);
                ov.y += res[c * 16 + 4 * j + 1] + w3 * eluf(acc[4 * j + 1]);
                ov.z += res[c * 16 + 4 * j + 2] + w3 * eluf(acc[4 * j + 2]);
                ov.w += res[c * 16 + 4 * j + 3] + w3 * eluf(acc[4 * j + 3]);
                o4[cc * 4 + j] = ov;
            }
        }
    }
}

// ---------------- host launcher ----------------
extern "C" void kernel_launch(void* const* d_in, const int* in_sizes, int n_in,
                              void* d_out, int out_size) {
    const float* x     = (const float*)d_in[0];
    const float* wts   = (const float*)d_in[1];
    const float* Wmlp  = (const float*)d_in[2];
    const float* bmlp  = (const float*)d_in[3];
    const float* Wl    = (const float*)d_in[4];
    const float* Wr    = (const float*)d_in[5];
    const float* bsage = (const float*)d_in[6];
    const float* Wgcn  = (const float*)d_in[7];
    const float* bgcn  = (const float*)d_in[8];
    const float* Wgat  = (const float*)d_in[9];
    const float* asrc  = (const float*)d_in[10];
    const float* adst  = (const float*)d_in[11];
    const float* bgat  = (const float*)d_in[12];
    const float* Wcheb = (const float*)d_in[13];
    const float* bcheb = (const float*)d_in[14];
    const float* Wgin  = (const float*)d_in[15];
    const float* bgin  = (const float*)d_in[16];
    const void*  eidx  = d_in[17];
    float* out = (float*)d_out;

    int N = in_sizes[0] / 64;
    if (N > NMAX) N = NMAX;
    int E = in_sizes[17] / 2;
    if (E > EMAX) E = EMAX;

    int nb_node = (N + 127) / 128;
    int nb_warp = (N * 32 + 255) / 256;
    int G = (N + 255) / 256;

    kinit<<<G, 256>>>((const int*)eidx, N);
    kconvert<<<(E + 255) / 256, 256>>>(eidx, E);
    kvec<<<1, 64>>>(Wgat, asrc, adst);
    kbsum<<<G, 256>>>(N);
    kbscan<<<1, 256>>>(G);
    kapply<<<G, 256>>>(N, E);
    kscatter<<<(E + 255) / 256, 256>>>(E);
    k1a<<<nb_node, 256>>>(x, wts, Wmlp, bmlp, Wr, bsage, out, N);
    kaggA<<<nb_warp, 256>>>(x, N);
    k1b<<<nb_node, 256>>>(x, wts, Wl, Wgin, bgin, out, N);
    kaggB<<<nb_warp, 256>>>(N);
    kf<<<nb_node, 256>>>(x, wts, Wcheb, bcheb, Wgcn, bgcn, Wgat, bgat, out, N);
}

// round 10
// speedup vs baseline: 1.7662x; 1.0268x over previous
#include <cuda_runtime.h>

#define NMAX 50000
#define EMAX 800000

// ---------------- scratch ----------------
__device__ __align__(16) int   g_ssrc[EMAX];
__device__ __align__(16) int   g_src[EMAX];
__device__ __align__(16) int   g_dst[EMAX];
__device__ __align__(16) int   g_rank[EMAX];
__device__ __align__(16) int   g_hist[NMAX];
__device__ __align__(16) int   g_rowptr[NMAX + 1];
__device__ __align__(16) int   g_bsum[256];
__device__ __align__(16) int   g_boff[256];
__device__ int   g_is64;
__device__ __align__(16) float g_vsrc[64];
__device__ __align__(16) float g_vdst[64];
__device__ __align__(16) float g_deg[NMAX];
__device__ __align__(16) float g_dinv[NMAX];
__device__ __align__(16) float g_dinvc[NMAX];
__device__ __align__(16) float g_el[NMAX];
__device__ __align__(16) float g_er[NMAX];
__device__ __align__(16) float g_m[NMAX];
__device__ __align__(16) float g_z[NMAX];
__device__ __align__(16) float g_nsum[NMAX * 64];
__device__ __align__(16) float g_gcnx[NMAX * 64];
__device__ __align__(16) float g_t1[NMAX * 64];
__device__ __align__(16) float g_t2[NMAX * 64];
__device__ __align__(16) float g_gatx[NMAX * 64];
__device__ __align__(16) float g_accsage[NMAX * 64];

// ---------------- helpers ----------------
__device__ __forceinline__ float eluf(float v) { return v > 0.f ? v : expm1f(v); }
__device__ __forceinline__ float leakyf(float v) { return v > 0.f ? v : 0.2f * v; }

__device__ __forceinline__ unsigned long long pack2(float lo, float hi) {
    unsigned long long r;
    asm("mov.b64 %0, {%1, %2};" : "=l"(r) : "f"(lo), "f"(hi));
    return r;
}
__device__ __forceinline__ float2 unpack2(unsigned long long v) {
    float lo, hi;
    asm("mov.b64 {%0, %1}, %2;" : "=f"(lo), "=f"(hi) : "l"(v));
    return make_float2(lo, hi);
}
#define FMA2(acc, w, xx) \
    asm("fma.rn.f32x2 %0, %1, %2, %0;" : "+l"(acc) : "l"(w), "l"(xx))

// load 64x64 fp32 matrix into smem (256 threads)
__device__ __forceinline__ void loadW(float* Wsm, const float* __restrict__ Wg, int t) {
    const float4* s = (const float4*)Wg;
    float4* d = (float4*)Wsm;
#pragma unroll
    for (int i = 0; i < 4; i++) d[t + i * 256] = s[t + i * 256];
}

__device__ __forceinline__ void gemv16x2(const float* __restrict__ Wsm,
                                         const float4* __restrict__ Xs,
                                         int tt, int jbase,
                                         unsigned long long acc2[8]) {
#pragma unroll 4
    for (int k4 = 0; k4 < 16; k4++) {
        float4 xq = Xs[k4 * 128 + tt];
#pragma unroll
        for (int s = 0; s < 4; s++) {
            float xv = (s == 0) ? xq.x : (s == 1) ? xq.y : (s == 2) ? xq.z : xq.w;
            unsigned long long xx = pack2(xv, xv);
            const ulonglong2* wp = (const ulonglong2*)(Wsm + (k4 * 4 + s) * 64 + jbase);
            ulonglong2 a = wp[0], b = wp[1], c = wp[2], d = wp[3];
            FMA2(acc2[0], a.x, xx); FMA2(acc2[1], a.y, xx);
            FMA2(acc2[2], b.x, xx); FMA2(acc2[3], b.y, xx);
            FMA2(acc2[4], c.x, xx); FMA2(acc2[5], c.y, xx);
            FMA2(acc2[6], d.x, xx); FMA2(acc2[7], d.y, xx);
        }
    }
}

__device__ __forceinline__ void accInitBias(unsigned long long a[8],
                                            const float* __restrict__ b) {
#pragma unroll
    for (int j = 0; j < 8; j++) a[j] = pack2(b[2 * j], b[2 * j + 1]);
}
__device__ __forceinline__ void accInitZero(unsigned long long a[8]) {
#pragma unroll
    for (int j = 0; j < 8; j++) a[j] = 0ull;
}
__device__ __forceinline__ void accOut(const unsigned long long a[8], float o[16]) {
#pragma unroll
    for (int j = 0; j < 8; j++) {
        float2 p = unpack2(a[j]);
        o[2 * j] = p.x;
        o[2 * j + 1] = p.y;
    }
}

__device__ __forceinline__ void loadXs(float4* Xs, const float4* __restrict__ row,
                                       int tt, int half) {
#pragma unroll
    for (int i = 0; i < 8; i++) {
        int k4 = half * 8 + i;
        Xs[k4 * 128 + tt] = row[k4];
    }
}

// ---------------- CSR build ----------------
__global__ void kinit(const int* __restrict__ raw, int N) {
    int i = blockIdx.x * blockDim.x + threadIdx.x;
    if (i < N) g_hist[i] = 0;
    if (i == 0) {
        int acc = 0;
        for (int k = 0; k < 64; k++) acc |= raw[2 * k + 1];
        g_is64 = (acc == 0) ? 1 : 0;
    }
}

__global__ void kconvert(const void* __restrict__ raw, int E) {
    int is64 = g_is64;
    for (int e = blockIdx.x * blockDim.x + threadIdx.x; e < E;
         e += gridDim.x * blockDim.x) {
        int s, d;
        if (is64) {
            const long long* p = (const long long*)raw;
            s = (int)p[e];
            d = (int)p[(size_t)E + e];
        } else {
            const int* p = (const int*)raw;
            s = p[e];
            d = p[E + e];
        }
        g_src[e] = s;
        g_dst[e] = d;
        g_rank[e] = atomicAdd(&g_hist[d], 1);  // rank doubles as scatter slot
    }
}

__global__ void kvec(const float* __restrict__ Wgat,
                     const float* __restrict__ asrc,
                     const float* __restrict__ adst) {
    int k = threadIdx.x;
    if (k < 64) {
        float s1 = 0.f, s2 = 0.f;
        const float* row = Wgat + k * 64;
        for (int j = 0; j < 64; j++) {
            float w = row[j];
            s1 += w * asrc[j];
            s2 += w * adst[j];
        }
        g_vsrc[k] = s1;
        g_vdst[k] = s2;
    }
}

__global__ __launch_bounds__(256) void kbsum(int N) {
    __shared__ int red[256];
    int t = threadIdx.x;
    int i = blockIdx.x * 256 + t;
    red[t] = (i < N) ? g_hist[i] : 0;
    __syncthreads();
    for (int o = 128; o; o >>= 1) {
        if (t < o) red[t] += red[t + o];
        __syncthreads();
    }
    if (t == 0) g_bsum[blockIdx.x] = red[0];
}

__global__ __launch_bounds__(256) void kbscan(int G) {
    __shared__ int s[256];
    int t = threadIdx.x;
    int v = (t < G) ? g_bsum[t] : 0;
    s[t] = v;
    __syncthreads();
    for (int o = 1; o < 256; o <<= 1) {
        int u = (t >= o) ? s[t - o] : 0;
        __syncthreads();
        s[t] += u;
        __syncthreads();
    }
    if (t < G) g_boff[t] = s[t] - v;
}

__global__ __launch_bounds__(256) void kapply(int N, int E) {
    __shared__ int wsum[8];
    int t = threadIdx.x;
    int lane = t & 31, wid = t >> 5;
    int i = blockIdx.x * 256 + t;
    int h = (i < N) ? g_hist[i] : 0;
    int val = h;
#pragma unroll
    for (int o = 1; o < 32; o <<= 1) {
        int u = __shfl_up_sync(0xffffffffu, val, o);
        if (lane >= o) val += u;
    }
    if (lane == 31) wsum[wid] = val;
    __syncthreads();
    if (t < 8) {
        int w = wsum[t];
#pragma unroll
        for (int o = 1; o < 8; o <<= 1) {
            int u = __shfl_up_sync(0xffu, w, o);
            if (t >= o) w += u;
        }
        wsum[t] = w;
    }
    __syncthreads();
    int excl = val - h + (wid ? wsum[wid - 1] : 0) + g_boff[blockIdx.x];
    if (i < N) {
        g_rowptr[i] = excl;
        float deg = (float)h;
        g_deg[i] = deg;
        g_dinv[i] = rsqrtf(deg + 1.f);
        g_dinvc[i] = rsqrtf(fmaxf(deg, 1.f));
    }
    if (i == 0) g_rowptr[N] = E;
}

// atomic-free scatter using precomputed rank
__global__ void kscatter(int E) {
    int e = blockIdx.x * blockDim.x + threadIdx.x;
    if (e >= E) return;
    g_ssrc[g_rowptr[g_dst[e]] + g_rank[e]] = g_src[e];
}

// ---------------- node kernel 1a: mlp + sage-r GEMVs, el/er dots ------------
__global__ __launch_bounds__(256) void k1a(
    const float* __restrict__ x, const float* __restrict__ wts,
    const float* __restrict__ Wmlp, const float* __restrict__ bmlp,
    const float* __restrict__ Wr, const float* __restrict__ bsage,
    float* __restrict__ out, int N) {
    __shared__ __align__(16) float Wsm[4096];
    __shared__ float4 Xs[2048];
    __shared__ float vs[64], vd[64];
    __shared__ float els[128], ers[128];
    int t = threadIdx.x;
    int tt = t & 127, half = t >> 7;
    int node = blockIdx.x * 128 + tt;
    bool act = node < N;
    if (act) loadXs(Xs, (const float4*)(x + (size_t)node * 64), tt, half);
    if (t < 64) vs[t] = g_vsrc[t];
    else if (t < 128) vd[t - 64] = g_vdst[t - 64];
    loadW(Wsm, Wmlp, t);
    __syncthreads();
    {
        float el = 0.f, er = 0.f;
        if (act) {
#pragma unroll
            for (int i = 0; i < 8; i++) {
                int k4 = half * 8 + i;
                float4 xq = Xs[k4 * 128 + tt];
                el += xq.x * vs[k4 * 4 + 0] + xq.y * vs[k4 * 4 + 1]
                    + xq.z * vs[k4 * 4 + 2] + xq.w * vs[k4 * 4 + 3];
                er += xq.x * vd[k4 * 4 + 0] + xq.y * vd[k4 * 4 + 1]
                    + xq.z * vd[k4 * 4 + 2] + xq.w * vd[k4 * 4 + 3];
            }
        }
        if (half == 1) { els[tt] = el; ers[tt] = er; }
        if (act) {
            float w0 = wts[0];
            float4* o4 = (float4*)(out + (size_t)node * 64);
#pragma unroll
            for (int c = 0; c < 2; c++) {
                int cc = half * 2 + c;
                unsigned long long a2[8];
                accInitBias(a2, bmlp + cc * 16);
                gemv16x2(Wsm, Xs, tt, cc * 16, a2);
                float acc[16];
                accOut(a2, acc);
#pragma unroll
                for (int j = 0; j < 4; j++)
                    o4[cc * 4 + j] = make_float4(w0 * eluf(acc[4 * j + 0]),
                                                 w0 * eluf(acc[4 * j + 1]),
                                                 w0 * eluf(acc[4 * j + 2]),
                                                 w0 * eluf(acc[4 * j + 3]));
            }
        }
        __syncthreads();
        if (half == 0 && act) {
            g_el[node] = el + els[tt];
            g_er[node] = er + ers[tt];
        }
    }
    loadW(Wsm, Wr, t);
    __syncthreads();
    if (act) {
        float4* o4 = (float4*)(g_accsage + (size_t)node * 64);
#pragma unroll
        for (int c = 0; c < 2; c++) {
            int cc = half * 2 + c;
            unsigned long long a2[8];
            accInitBias(a2, bsage + cc * 16);
            gemv16x2(Wsm, Xs, tt, cc * 16, a2);
            float acc[16];
            accOut(a2, acc);
#pragma unroll
            for (int j = 0; j < 4; j++)
                o4[cc * 4 + j] = make_float4(acc[4 * j], acc[4 * j + 1],
                                             acc[4 * j + 2], acc[4 * j + 3]);
        }
    }
}

// ---------------- gather pass A: 4 weighted sums of x rows -----------------
__global__ __launch_bounds__(256) void kaggA(const float* __restrict__ x, int N) {
    int gw = (blockIdx.x * 256 + threadIdx.x) >> 5;
    if (gw >= N) return;
    int lane = threadIdx.x & 31;
    int d = gw;
    int beg = g_rowptr[d], end = g_rowptr[d + 1];
    float erd = g_er[d];
    float dinvd = g_dinv[d], dinvcd = g_dinvc[d];
    float es = leakyf(g_el[d] + erd);
    float m = es;
    for (int e = beg + lane; e < end; e += 32)
        m = fmaxf(m, leakyf(g_el[g_ssrc[e]] + erd));
#pragma unroll
    for (int o = 16; o; o >>= 1) m = fmaxf(m, __shfl_xor_sync(0xffffffffu, m, o));

    float ns0 = 0, ns1 = 0, gc0 = 0, gc1 = 0, t10 = 0, t11 = 0, ga0 = 0, ga1 = 0;
    float zacc = 0.f;
    for (int base = beg; base < end; base += 32) {
        int n = min(32, end - base);
        int sj = 0;
        float pj = 0.f, wgj = 0.f, wtj = 0.f;
        if (lane < n) {
            sj = g_ssrc[base + lane];
            pj = expf(leakyf(g_el[sj] + erd) - m);
            wgj = g_dinv[sj] * dinvd;
            wtj = g_dinvc[sj] * dinvcd;
            zacc += pj;
        }
        for (int j = 0; j < n; j++) {
            int s = __shfl_sync(0xffffffffu, sj, j);
            float p = __shfl_sync(0xffffffffu, pj, j);
            float wg = __shfl_sync(0xffffffffu, wgj, j);
            float wt = __shfl_sync(0xffffffffu, wtj, j);
            float2 xv = ((const float2*)(x + (size_t)s * 64))[lane];
            ns0 += xv.x;       ns1 += xv.y;
            gc0 += wg * xv.x;  gc1 += wg * xv.y;
            t10 -= wt * xv.x;  t11 -= wt * xv.y;
            ga0 += p * xv.x;   ga1 += p * xv.y;
        }
    }
#pragma unroll
    for (int o = 16; o; o >>= 1) zacc += __shfl_xor_sync(0xffffffffu, zacc, o);
    float z = expf(es - m) + zacc;
    ((float2*)(g_nsum + (size_t)d * 64))[lane] = make_float2(ns0, ns1);
    ((float2*)(g_gcnx + (size_t)d * 64))[lane] = make_float2(gc0, gc1);
    ((float2*)(g_t1   + (size_t)d * 64))[lane] = make_float2(t10, t11);
    ((float2*)(g_gatx + (size_t)d * 64))[lane] = make_float2(ga0, ga1);
    if (lane == 0) { g_m[d] = m; g_z[d] = z; }
}

// ---------------- node kernel 1b: sage + gin finalize ----------------
__global__ __launch_bounds__(256) void k1b(const float* __restrict__ x,
                                           const float* __restrict__ wts,
                                           const float* __restrict__ Wl,
                                           const float* __restrict__ Wgin,
                                           const float* __restrict__ bgin,
                                           float* __restrict__ out, int N) {
    __shared__ __align__(16) float Wsm[4096];
    __shared__ float4 Xs[2048];
    int t = threadIdx.x;
    int tt = t & 127, half = t >> 7;
    int node = blockIdx.x * 128 + tt;
    bool act = node < N;
    float invd = 1.f;
    if (act) {
        loadXs(Xs, (const float4*)(g_nsum + (size_t)node * 64), tt, half);
        invd = 1.f / fmaxf(g_deg[node], 1.f);
    }
    loadW(Wsm, Wl, t);
    __syncthreads();
    if (act) {
        float w1 = wts[1];
        float4* o4 = (float4*)(out + (size_t)node * 64);
        const float4* as4 = (const float4*)(g_accsage + (size_t)node * 64);
#pragma unroll
        for (int c = 0; c < 2; c++) {
            int cc = half * 2 + c;
            unsigned long long a2[8];
            accInitZero(a2);
            gemv16x2(Wsm, Xs, tt, cc * 16, a2);
            float acc[16];
            accOut(a2, acc);
#pragma unroll
            for (int j = 0; j < 4; j++) {
                float4 ov = o4[cc * 4 + j];
                float4 as = as4[cc * 4 + j];
                ov.x += w1 * eluf(acc[4 * j + 0] * invd + as.x);
                ov.y += w1 * eluf(acc[4 * j + 1] * invd + as.y);
                ov.z += w1 * eluf(acc[4 * j + 2] * invd + as.z);
                ov.w += w1 * eluf(acc[4 * j + 3] * invd + as.w);
                o4[cc * 4 + j] = ov;
            }
        }
    }
    __syncthreads();
    if (act) {
        const float4* xr = (const float4*)(x + (size_t)node * 64);
#pragma unroll
        for (int i = 0; i < 8; i++) {
            int k4 = half * 8 + i;
            float4 v = Xs[k4 * 128 + tt];
            float4 a = xr[k4];
            Xs[k4 * 128 + tt] = make_float4(v.x + a.x, v.y + a.y, v.z + a.z, v.w + a.w);
        }
    }
    loadW(Wsm, Wgin, t);
    __syncthreads();
    if (act) {
        float w5 = wts[5];
        float4* o4 = (float4*)(out + (size_t)node * 64);
#pragma unroll
        for (int c = 0; c < 2; c++) {
            int cc = half * 2 + c;
            unsigned long long a2[8];
            accInitBias(a2, bgin + cc * 16);
            gemv16x2(Wsm, Xs, tt, cc * 16, a2);
            float acc[16];
            accOut(a2, acc);
#pragma unroll
            for (int j = 0; j < 4; j++) {
                float4 ov = o4[cc * 4 + j];
                ov.x += w5 * eluf(acc[4 * j + 0]);
                ov.y += w5 * eluf(acc[4 * j + 1]);
                ov.z += w5 * eluf(acc[4 * j + 2]);
                ov.w += w5 * eluf(acc[4 * j + 3]);
                o4[cc * 4 + j] = ov;
            }
        }
    }
}

// ---------------- gather pass B: Cheb T2 acc = prop(T1) ----------------
__global__ __launch_bounds__(256) void kaggB(int N) {
    int gw = (blockIdx.x * 256 + threadIdx.x) >> 5;
    if (gw >= N) return;
    int lane = threadIdx.x & 31;
    int d = gw;
    int beg = g_rowptr[d], end = g_rowptr[d + 1];
    float dinvcd = g_dinvc[d];
    float t20 = 0.f, t21 = 0.f;
    for (int base = beg; base < end; base += 32) {
        int n = min(32, end - base);
        int sj = 0;
        float wtj = 0.f;
        if (lane < n) {
            sj = g_ssrc[base + lane];
            wtj = g_dinvc[sj] * dinvcd;
        }
        for (int j = 0; j < n; j++) {
            int s = __shfl_sync(0xffffffffu, sj, j);
            float wt = __shfl_sync(0xffffffffu, wtj, j);
            float2 v = ((const float2*)(g_t1 + (size_t)s * 64))[lane];
            t20 += wt * v.x;
            t21 += wt * v.y;
        }
    }
    ((float2*)(g_t2 + (size_t)d * 64))[lane] = make_float2(t20, t21);
}

// ---------------- final node kernel: cheb(3) + gcn + gat -------------------
__global__ __launch_bounds__(256) void kf(const float* __restrict__ x,
                                          const float* __restrict__ wts,
                                          const float* __restrict__ Wcheb,
                                          const float* __restrict__ bcheb,
                                          const float* __restrict__ Wgcn,
                                          const float* __restrict__ bgcn,
                                          const float* __restrict__ Wgat,
                                          const float* __restrict__ bgat,
                                          float* __restrict__ out, int N) {
    __shared__ __align__(16) float Wsm[4096];
    __shared__ float4 Xs[2048];
    int t = threadIdx.x;
    int tt = t & 127, half = t >> 7;
    int node = blockIdx.x * 128 + tt;
    bool act = node < N;
    float res[32];
    if (act) loadXs(Xs, (const float4*)(x + (size_t)node * 64), tt, half);
    loadW(Wsm, Wcheb, t);
    __syncthreads();
    if (act) {
#pragma unroll
        for (int c = 0; c < 2; c++) {
            int cc = half * 2 + c;
            unsigned long long a2[8];
            accInitBias(a2, bcheb + cc * 16);
            gemv16x2(Wsm, Xs, tt, cc * 16, a2);
            accOut(a2, res + c * 16);
        }
    }
    __syncthreads();
    if (act) loadXs(Xs, (const float4*)(g_t1 + (size_t)node * 64), tt, half);
    loadW(Wsm, Wcheb + 4096, t);
    __syncthreads();
    if (act) {
#pragma unroll
        for (int c = 0; c < 2; c++) {
            int cc = half * 2 + c;
            unsigned long long a2[8];
            accInitZero(a2);
            gemv16x2(Wsm, Xs, tt, cc * 16, a2);
            float acc[16];
            accOut(a2, acc);
#pragma unroll
            for (int j = 0; j < 16; j++) res[c * 16 + j] += acc[j];
        }
    }
    __syncthreads();
    if (act) {
        const float4* xr = (const float4*)(x + (size_t)node * 64);
        const float4* t2r = (const float4*)(g_t2 + (size_t)node * 64);
#pragma unroll
        for (int i = 0; i < 8; i++) {
            int k4 = half * 8 + i;
            float4 a = xr[k4];
            float4 b = t2r[k4];
            Xs[k4 * 128 + tt] = make_float4(-2.f * b.x - a.x, -2.f * b.y - a.y,
                                            -2.f * b.z - a.z, -2.f * b.w - a.w);
        }
    }
    loadW(Wsm, Wcheb + 8192, t);
    __syncthreads();
    float w2 = wts[2], w3 = wts[3], w4 = wts[4];
    if (act) {
#pragma unroll
        for (int c = 0; c < 2; c++) {
            int cc = half * 2 + c;
            unsigned long long a2[8];
            accInitZero(a2);
            gemv16x2(Wsm, Xs, tt, cc * 16, a2);
            float acc[16];
            accOut(a2, acc);
#pragma unroll
            for (int j = 0; j < 16; j++)
                res[c * 16 + j] = w4 * eluf(res[c * 16 + j] + acc[j]);
        }
    }
    __syncthreads();
    if (act) {
        float dinv = g_dinv[node];
        float di2 = dinv * dinv;
        const float4* xr = (const float4*)(x + (size_t)node * 64);
        const float4* gr = (const float4*)(g_gcnx + (size_t)node * 64);
#pragma unroll
        for (int i = 0; i < 8; i++) {
            int k4 = half * 8 + i;
            float4 a = xr[k4];
            float4 g = gr[k4];
            Xs[k4 * 128 + tt] = make_float4(g.x + di2 * a.x, g.y + di2 * a.y,
                                            g.z + di2 * a.z, g.w + di2 * a.w);
        }
    }
    loadW(Wsm, Wgcn, t);
    __syncthreads();
    if (act) {
#pragma unroll
        for (int c = 0; c < 2; c++) {
            int cc = half * 2 + c;
            unsigned long long a2[8];
            accInitBias(a2, bgcn + cc * 16);
            gemv16x2(Wsm, Xs, tt, cc * 16, a2);
            float acc[16];
            accOut(a2, acc);
#pragma unroll
            for (int j = 0; j < 16; j++) res[c * 16 + j] += w2 * eluf(acc[j]);
        }
    }
    __syncthreads();
    if (act) {
        float es = leakyf(g_el[node] + g_er[node]);
        float cs = expf(es - g_m[node]);
        float invz = 1.f / (g_z[node] + 1e-16f);
        const float4* xr = (const float4*)(x + (size_t)node * 64);
        const float4* gr = (const float4*)(g_gatx + (size_t)node * 64);
#pragma unroll
        for (int i = 0; i < 8; i++) {
            int k4 = half * 8 + i;
            float4 a = xr[k4];
            float4 g = gr[k4];
            Xs[k4 * 128 + tt] = make_float4(invz * (g.x + cs * a.x),
                                            invz * (g.y + cs * a.y),
                                            invz * (g.z + cs * a.z),
                                            invz * (g.w + cs * a.w));
        }
    }
    loadW(Wsm, Wgat, t);
    __syncthreads();
    if (act) {
        float4* o4 = (float4*)(out + (size_t)node * 64);
#pragma unroll
        for (int c = 0; c < 2; c++) {
            int cc = half * 2 + c;
            unsigned long long a2[8];
            accInitBias(a2, bgat + cc * 16);
            gemv16x2(Wsm, Xs, tt, cc * 16, a2);
            float acc[16];
            accOut(a2, acc);
#pragma unroll
            for (int j = 0; j < 4; j++) {
                float4 ov = o4[cc * 4 + j];
                ov.x += res[c * 16 + 4 * j + 0] + w3 * eluf(acc[4 * j + 0]);
                ov.y += res[c * 16 + 4 * j + 1] + w3 * eluf(acc[4 * j + 1]);
                ov.z += res[c * 16 + 4 * j + 2] + w3 * eluf(acc[4 * j + 2]);
                ov.w += res[c * 16 + 4 * j + 3] + w3 * eluf(acc[4 * j + 3]);
                o4[cc * 4 + j] = ov;
            }
        }
    }
}

// ---------------- host launcher (graph-capture stream forking) --------------
extern "C" void kernel_launch(void* const* d_in, const int* in_sizes, int n_in,
                              void* d_out, int out_size) {
    static cudaStream_t s1 = nullptr;
    static cudaEvent_t ev_fork = nullptr, ev_a = nullptr, ev_b = nullptr, ev_j = nullptr;
    if (s1 == nullptr) {
        cudaStreamCreateWithFlags(&s1, cudaStreamNonBlocking);
        cudaEventCreateWithFlags(&ev_fork, cudaEventDisableTiming);
        cudaEventCreateWithFlags(&ev_a, cudaEventDisableTiming);
        cudaEventCreateWithFlags(&ev_b, cudaEventDisableTiming);
        cudaEventCreateWithFlags(&ev_j, cudaEventDisableTiming);
    }

    const float* x     = (const float*)d_in[0];
    const float* wts   = (const float*)d_in[1];
    const float* Wmlp  = (const float*)d_in[2];
    const float* bmlp  = (const float*)d_in[3];
    const float* Wl    = (const float*)d_in[4];
    const float* Wr    = (const float*)d_in[5];
    const float* bsage = (const float*)d_in[6];
    const float* Wgcn  = (const float*)d_in[7];
    const float* bgcn  = (const float*)d_in[8];
    const float* Wgat  = (const float*)d_in[9];
    const float* asrc  = (const float*)d_in[10];
    const float* adst  = (const float*)d_in[11];
    const float* bgat  = (const float*)d_in[12];
    const float* Wcheb = (const float*)d_in[13];
    const float* bcheb = (const float*)d_in[14];
    const float* Wgin  = (const float*)d_in[15];
    const float* bgin  = (const float*)d_in[16];
    const void*  eidx  = d_in[17];
    float* out = (float*)d_out;

    int N = in_sizes[0] / 64;
    if (N > NMAX) N = NMAX;
    int E = in_sizes[17] / 2;
    if (E > EMAX) E = EMAX;

    int nb_node = (N + 127) / 128;
    int nb_warp = (N * 32 + 255) / 256;
    int G = (N + 255) / 256;
    int nbE = (E + 255) / 256;

    // fork: s1 does kvec + k1a (x-only) while main stream builds CSR
    cudaEventRecord(ev_fork, 0);
    cudaStreamWaitEvent(s1, ev_fork, 0);
    kvec<<<1, 64, 0, s1>>>(Wgat, asrc, adst);
    k1a<<<nb_node, 256, 0, s1>>>(x, wts, Wmlp, bmlp, Wr, bsage, out, N);
    cudaEventRecord(ev_a, s1);

    kinit<<<G, 256>>>((const int*)eidx, N);
    kconvert<<<nbE, 256>>>(eidx, E);
    kbsum<<<G, 256>>>(N);
    kbscan<<<1, 256>>>(G);
    kapply<<<G, 256>>>(N, E);
    kscatter<<<nbE, 256>>>(E);

    // join, then the big gather
    cudaStreamWaitEvent(0, ev_a, 0);
    kaggA<<<nb_warp, 256>>>(x, N);

    // fork: k1b (out) on s1 in parallel with kaggB (t2) on main
    cudaEventRecord(ev_b, 0);
    cudaStreamWaitEvent(s1, ev_b, 0);
    k1b<<<nb_node, 256, 0, s1>>>(x, wts, Wl, Wgin, bgin, out, N);
    cudaEventRecord(ev_j, s1);

    kaggB<<<nb_warp, 256>>>(N);

    // join and finish
    cudaStreamWaitEvent(0, ev_j, 0);
    kf<<<nb_node, 256>>>(x, wts, Wcheb, bcheb, Wgcn, bgcn, Wgat, bgat, out, N);
}

// round 11
// speedup vs baseline: 1.8149x; 1.0276x over previous
#include <cuda_runtime.h>

#define NMAX 50000
#define EMAX 800000

// ---------------- scratch ----------------
__device__ __align__(16) int   g_ssrc[EMAX];
__device__ __align__(16) int   g_src[EMAX];
__device__ __align__(16) int   g_dst[EMAX];
__device__ __align__(16) int   g_rank[EMAX];
__device__ __align__(16) int   g_hist[NMAX];
__device__ __align__(16) int   g_rowptr[NMAX + 1];
__device__ __align__(16) int   g_bsum[256];
__device__ __align__(16) int   g_boff[256];
__device__ int   g_is64;
__device__ __align__(16) float g_vsrc[64];
__device__ __align__(16) float g_vdst[64];
__device__ __align__(16) float g_deg[NMAX];
__device__ __align__(16) float g_dinv[NMAX];
__device__ __align__(16) float g_dinvc[NMAX];
__device__ __align__(16) float g_el[NMAX];
__device__ __align__(16) float g_er[NMAX];
__device__ __align__(16) float g_z[NMAX];
__device__ __align__(16) float g_nsum[NMAX * 64];
__device__ __align__(16) float g_gcnx[NMAX * 64];
__device__ __align__(16) float g_t1[NMAX * 64];
__device__ __align__(16) float g_t2[NMAX * 64];
__device__ __align__(16) float g_gatx[NMAX * 64];
__device__ __align__(16) float g_accsage[NMAX * 64];

// ---------------- helpers ----------------
__device__ __forceinline__ float eluf(float v) { return v > 0.f ? v : expm1f(v); }
__device__ __forceinline__ float leakyf(float v) { return v > 0.f ? v : 0.2f * v; }

__device__ __forceinline__ unsigned long long pack2(float lo, float hi) {
    unsigned long long r;
    asm("mov.b64 %0, {%1, %2};" : "=l"(r) : "f"(lo), "f"(hi));
    return r;
}
__device__ __forceinline__ float2 unpack2(unsigned long long v) {
    float lo, hi;
    asm("mov.b64 {%0, %1}, %2;" : "=f"(lo), "=f"(hi) : "l"(v));
    return make_float2(lo, hi);
}
#define FMA2(acc, w, xx) \
    asm("fma.rn.f32x2 %0, %1, %2, %0;" : "+l"(acc) : "l"(w), "l"(xx))
#define ADD2(acc, xx) \
    asm("add.rn.f32x2 %0, %0, %1;" : "+l"(acc) : "l"(xx))

// load 64x64 fp32 matrix into smem (256 threads)
__device__ __forceinline__ void loadW(float* Wsm, const float* __restrict__ Wg, int t) {
    const float4* s = (const float4*)Wg;
    float4* d = (float4*)Wsm;
#pragma unroll
    for (int i = 0; i < 4; i++) d[t + i * 256] = s[t + i * 256];
}

__device__ __forceinline__ void gemv16x2(const float* __restrict__ Wsm,
                                         const float4* __restrict__ Xs,
                                         int tt, int jbase,
                                         unsigned long long acc2[8]) {
#pragma unroll 4
    for (int k4 = 0; k4 < 16; k4++) {
        float4 xq = Xs[k4 * 128 + tt];
#pragma unroll
        for (int s = 0; s < 4; s++) {
            float xv = (s == 0) ? xq.x : (s == 1) ? xq.y : (s == 2) ? xq.z : xq.w;
            unsigned long long xx = pack2(xv, xv);
            const ulonglong2* wp = (const ulonglong2*)(Wsm + (k4 * 4 + s) * 64 + jbase);
            ulonglong2 a = wp[0], b = wp[1], c = wp[2], d = wp[3];
            FMA2(acc2[0], a.x, xx); FMA2(acc2[1], a.y, xx);
            FMA2(acc2[2], b.x, xx); FMA2(acc2[3], b.y, xx);
            FMA2(acc2[4], c.x, xx); FMA2(acc2[5], c.y, xx);
            FMA2(acc2[6], d.x, xx); FMA2(acc2[7], d.y, xx);
        }
    }
}

__device__ __forceinline__ void accInitBias(unsigned long long a[8],
                                            const float* __restrict__ b) {
#pragma unroll
    for (int j = 0; j < 8; j++) a[j] = pack2(b[2 * j], b[2 * j + 1]);
}
__device__ __forceinline__ void accInitZero(unsigned long long a[8]) {
#pragma unroll
    for (int j = 0; j < 8; j++) a[j] = 0ull;
}
__device__ __forceinline__ void accOut(const unsigned long long a[8], float o[16]) {
#pragma unroll
    for (int j = 0; j < 8; j++) {
        float2 p = unpack2(a[j]);
        o[2 * j] = p.x;
        o[2 * j + 1] = p.y;
    }
}

__device__ __forceinline__ void loadXs(float4* Xs, const float4* __restrict__ row,
                                       int tt, int half) {
#pragma unroll
    for (int i = 0; i < 8; i++) {
        int k4 = half * 8 + i;
        Xs[k4 * 128 + tt] = row[k4];
    }
}

// ---------------- CSR build ----------------
__global__ void kinit(const int* __restrict__ raw, int N) {
    int i = blockIdx.x * blockDim.x + threadIdx.x;
    if (i < N) g_hist[i] = 0;
    if (i == 0) {
        int acc = 0;
        for (int k = 0; k < 64; k++) acc |= raw[2 * k + 1];
        g_is64 = (acc == 0) ? 1 : 0;
    }
}

__global__ void kconvert(const void* __restrict__ raw, int E) {
    int is64 = g_is64;
    for (int e = blockIdx.x * blockDim.x + threadIdx.x; e < E;
         e += gridDim.x * blockDim.x) {
        int s, d;
        if (is64) {
            const long long* p = (const long long*)raw;
            s = (int)p[e];
            d = (int)p[(size_t)E + e];
        } else {
            const int* p = (const int*)raw;
            s = p[e];
            d = p[E + e];
        }
        g_src[e] = s;
        g_dst[e] = d;
        g_rank[e] = atomicAdd(&g_hist[d], 1);
    }
}

__global__ void kvec(const float* __restrict__ Wgat,
                     const float* __restrict__ asrc,
                     const float* __restrict__ adst) {
    int k = threadIdx.x;
    if (k < 64) {
        float s1 = 0.f, s2 = 0.f;
        const float* row = Wgat + k * 64;
        for (int j = 0; j < 64; j++) {
            float w = row[j];
            s1 += w * asrc[j];
            s2 += w * adst[j];
        }
        g_vsrc[k] = s1;
        g_vdst[k] = s2;
    }
}

__global__ __launch_bounds__(256) void kbsum(int N) {
    __shared__ int red[256];
    int t = threadIdx.x;
    int i = blockIdx.x * 256 + t;
    red[t] = (i < N) ? g_hist[i] : 0;
    __syncthreads();
    for (int o = 128; o; o >>= 1) {
        if (t < o) red[t] += red[t + o];
        __syncthreads();
    }
    if (t == 0) g_bsum[blockIdx.x] = red[0];
}

__global__ __launch_bounds__(256) void kbscan(int G) {
    __shared__ int s[256];
    int t = threadIdx.x;
    int v = (t < G) ? g_bsum[t] : 0;
    s[t] = v;
    __syncthreads();
    for (int o = 1; o < 256; o <<= 1) {
        int u = (t >= o) ? s[t - o] : 0;
        __syncthreads();
        s[t] += u;
        __syncthreads();
    }
    if (t < G) g_boff[t] = s[t] - v;
}

__global__ __launch_bounds__(256) void kapply(int N, int E) {
    __shared__ int wsum[8];
    int t = threadIdx.x;
    int lane = t & 31, wid = t >> 5;
    int i = blockIdx.x * 256 + t;
    int h = (i < N) ? g_hist[i] : 0;
    int val = h;
#pragma unroll
    for (int o = 1; o < 32; o <<= 1) {
        int u = __shfl_up_sync(0xffffffffu, val, o);
        if (lane >= o) val += u;
    }
    if (lane == 31) wsum[wid] = val;
    __syncthreads();
    if (t < 8) {
        int w = wsum[t];
#pragma unroll
        for (int o = 1; o < 8; o <<= 1) {
            int u = __shfl_up_sync(0xffu, w, o);
            if (t >= o) w += u;
        }
        wsum[t] = w;
    }
    __syncthreads();
    int excl = val - h + (wid ? wsum[wid - 1] : 0) + g_boff[blockIdx.x];
    if (i < N) {
        g_rowptr[i] = excl;
        float deg = (float)h;
        g_deg[i] = deg;
        g_dinv[i] = rsqrtf(deg + 1.f);
        g_dinvc[i] = rsqrtf(fmaxf(deg, 1.f));
    }
    if (i == 0) g_rowptr[N] = E;
}

__global__ void kscatter(int E) {
    int e = blockIdx.x * blockDim.x + threadIdx.x;
    if (e >= E) return;
    g_ssrc[g_rowptr[g_dst[e]] + g_rank[e]] = g_src[e];
}

// ---------------- node kernel 1a: mlp + sage-r GEMVs, el/er dots ------------
__global__ __launch_bounds__(256) void k1a(
    const float* __restrict__ x, const float* __restrict__ wts,
    const float* __restrict__ Wmlp, const float* __restrict__ bmlp,
    const float* __restrict__ Wr, const float* __restrict__ bsage,
    float* __restrict__ out, int N) {
    __shared__ __align__(16) float Wsm[4096];
    __shared__ float4 Xs[2048];
    __shared__ float vs[64], vd[64];
    __shared__ float els[128], ers[128];
    int t = threadIdx.x;
    int tt = t & 127, half = t >> 7;
    int node = blockIdx.x * 128 + tt;
    bool act = node < N;
    if (act) loadXs(Xs, (const float4*)(x + (size_t)node * 64), tt, half);
    if (t < 64) vs[t] = g_vsrc[t];
    else if (t < 128) vd[t - 64] = g_vdst[t - 64];
    loadW(Wsm, Wmlp, t);
    __syncthreads();
    {
        float el = 0.f, er = 0.f;
        if (act) {
#pragma unroll
            for (int i = 0; i < 8; i++) {
                int k4 = half * 8 + i;
                float4 xq = Xs[k4 * 128 + tt];
                el += xq.x * vs[k4 * 4 + 0] + xq.y * vs[k4 * 4 + 1]
                    + xq.z * vs[k4 * 4 + 2] + xq.w * vs[k4 * 4 + 3];
                er += xq.x * vd[k4 * 4 + 0] + xq.y * vd[k4 * 4 + 1]
                    + xq.z * vd[k4 * 4 + 2] + xq.w * vd[k4 * 4 + 3];
            }
        }
        if (half == 1) { els[tt] = el; ers[tt] = er; }
        if (act) {
            float w0 = wts[0];
            float4* o4 = (float4*)(out + (size_t)node * 64);
#pragma unroll
            for (int c = 0; c < 2; c++) {
                int cc = half * 2 + c;
                unsigned long long a2[8];
                accInitBias(a2, bmlp + cc * 16);
                gemv16x2(Wsm, Xs, tt, cc * 16, a2);
                float acc[16];
                accOut(a2, acc);
#pragma unroll
                for (int j = 0; j < 4; j++)
                    o4[cc * 4 + j] = make_float4(w0 * eluf(acc[4 * j + 0]),
                                                 w0 * eluf(acc[4 * j + 1]),
                                                 w0 * eluf(acc[4 * j + 2]),
                                                 w0 * eluf(acc[4 * j + 3]));
            }
        }
        __syncthreads();
        if (half == 0 && act) {
            g_el[node] = el + els[tt];
            g_er[node] = er + ers[tt];
        }
    }
    loadW(Wsm, Wr, t);
    __syncthreads();
    if (act) {
        float4* o4 = (float4*)(g_accsage + (size_t)node * 64);
#pragma unroll
        for (int c = 0; c < 2; c++) {
            int cc = half * 2 + c;
            unsigned long long a2[8];
            accInitBias(a2, bsage + cc * 16);
            gemv16x2(Wsm, Xs, tt, cc * 16, a2);
            float acc[16];
            accOut(a2, acc);
#pragma unroll
            for (int j = 0; j < 4; j++)
                o4[cc * 4 + j] = make_float4(acc[4 * j], acc[4 * j + 1],
                                             acc[4 * j + 2], acc[4 * j + 3]);
        }
    }
}

// ---------------- gather pass A: 4 weighted sums of x rows (no max-shift) ---
__global__ __launch_bounds__(256) void kaggA(const float* __restrict__ x, int N) {
    int gw = (blockIdx.x * 256 + threadIdx.x) >> 5;
    if (gw >= N) return;
    int lane = threadIdx.x & 31;
    int d = gw;
    int beg = g_rowptr[d], end = g_rowptr[d + 1];
    float erd = g_er[d];
    float dinvd = g_dinv[d], dinvcd = g_dinvc[d];
    float es = leakyf(g_el[d] + erd);

    unsigned long long ns = 0ull, gc = 0ull, t1 = 0ull, ga = 0ull;
    float zacc = 0.f;
    for (int base = beg; base < end; base += 32) {
        int n = min(32, end - base);
        int sj = 0;
        float pj = 0.f, wgj = 0.f, wtj = 0.f;
        if (lane < n) {
            sj = g_ssrc[base + lane];
            pj = expf(leakyf(g_el[sj] + erd));
            wgj = g_dinv[sj] * dinvd;
            wtj = -g_dinvc[sj] * dinvcd;   // T1 = -prop(x): fold sign here
            zacc += pj;
        }
        for (int j = 0; j < n; j++) {
            int s = __shfl_sync(0xffffffffu, sj, j);
            float p = __shfl_sync(0xffffffffu, pj, j);
            float wg = __shfl_sync(0xffffffffu, wgj, j);
            float wt = __shfl_sync(0xffffffffu, wtj, j);
            float2 xv = ((const float2*)(x + (size_t)s * 64))[lane];
            unsigned long long xx = pack2(xv.x, xv.y);
            ADD2(ns, xx);
            FMA2(gc, pack2(wg, wg), xx);
            FMA2(t1, pack2(wt, wt), xx);
            FMA2(ga, pack2(p, p), xx);
        }
    }
#pragma unroll
    for (int o = 16; o; o >>= 1) zacc += __shfl_xor_sync(0xffffffffu, zacc, o);
    float z = expf(es) + zacc;
    float2 v;
    v = unpack2(ns); ((float2*)(g_nsum + (size_t)d * 64))[lane] = v;
    v = unpack2(gc); ((float2*)(g_gcnx + (size_t)d * 64))[lane] = v;
    v = unpack2(t1); ((float2*)(g_t1   + (size_t)d * 64))[lane] = v;
    v = unpack2(ga); ((float2*)(g_gatx + (size_t)d * 64))[lane] = v;
    if (lane == 0) g_z[d] = z;
}

// ---------------- node kernel 1b: sage + gin finalize ----------------
__global__ __launch_bounds__(256) void k1b(const float* __restrict__ x,
                                           const float* __restrict__ wts,
                                           const float* __restrict__ Wl,
                                           const float* __restrict__ Wgin,
                                           const float* __restrict__ bgin,
                                           float* __restrict__ out, int N) {
    __shared__ __align__(16) float Wsm[4096];
    __shared__ float4 Xs[2048];
    int t = threadIdx.x;
    int tt = t & 127, half = t >> 7;
    int node = blockIdx.x * 128 + tt;
    bool act = node < N;
    float invd = 1.f;
    if (act) {
        loadXs(Xs, (const float4*)(g_nsum + (size_t)node * 64), tt, half);
        invd = 1.f / fmaxf(g_deg[node], 1.f);
    }
    loadW(Wsm, Wl, t);
    __syncthreads();
    if (act) {
        float w1 = wts[1];
        float4* o4 = (float4*)(out + (size_t)node * 64);
        const float4* as4 = (const float4*)(g_accsage + (size_t)node * 64);
#pragma unroll
        for (int c = 0; c < 2; c++) {
            int cc = half * 2 + c;
            unsigned long long a2[8];
            accInitZero(a2);
            gemv16x2(Wsm, Xs, tt, cc * 16, a2);
            float acc[16];
            accOut(a2, acc);
#pragma unroll
            for (int j = 0; j < 4; j++) {
                float4 ov = o4[cc * 4 + j];
                float4 as = as4[cc * 4 + j];
                ov.x += w1 * eluf(acc[4 * j + 0] * invd + as.x);
                ov.y += w1 * eluf(acc[4 * j + 1] * invd + as.y);
                ov.z += w1 * eluf(acc[4 * j + 2] * invd + as.z);
                ov.w += w1 * eluf(acc[4 * j + 3] * invd + as.w);
                o4[cc * 4 + j] = ov;
            }
        }
    }
    __syncthreads();
    if (act) {
        const float4* xr = (const float4*)(x + (size_t)node * 64);
#pragma unroll
        for (int i = 0; i < 8; i++) {
            int k4 = half * 8 + i;
            float4 v = Xs[k4 * 128 + tt];
            float4 a = xr[k4];
            Xs[k4 * 128 + tt] = make_float4(v.x + a.x, v.y + a.y, v.z + a.z, v.w + a.w);
        }
    }
    loadW(Wsm, Wgin, t);
    __syncthreads();
    if (act) {
        float w5 = wts[5];
        float4* o4 = (float4*)(out + (size_t)node * 64);
#pragma unroll
        for (int c = 0; c < 2; c++) {
            int cc = half * 2 + c;
            unsigned long long a2[8];
            accInitBias(a2, bgin + cc * 16);
            gemv16x2(Wsm, Xs, tt, cc * 16, a2);
            float acc[16];
            accOut(a2, acc);
#pragma unroll
            for (int j = 0; j < 4; j++) {
                float4 ov = o4[cc * 4 + j];
                ov.x += w5 * eluf(acc[4 * j + 0]);
                ov.y += w5 * eluf(acc[4 * j + 1]);
                ov.z += w5 * eluf(acc[4 * j + 2]);
                ov.w += w5 * eluf(acc[4 * j + 3]);
                o4[cc * 4 + j] = ov;
            }
        }
    }
}

// ---------------- gather pass B: Cheb T2 acc = prop(T1) ----------------
__global__ __launch_bounds__(256) void kaggB(int N) {
    int gw = (blockIdx.x * 256 + threadIdx.x) >> 5;
    if (gw >= N) return;
    int lane = threadIdx.x & 31;
    int d = gw;
    int beg = g_rowptr[d], end = g_rowptr[d + 1];
    float dinvcd = g_dinvc[d];
    unsigned long long t2 = 0ull;
    for (int base = beg; base < end; base += 32) {
        int n = min(32, end - base);
        int sj = 0;
        float wtj = 0.f;
        if (lane < n) {
            sj = g_ssrc[base + lane];
            wtj = g_dinvc[sj] * dinvcd;
        }
        for (int j = 0; j < n; j++) {
            int s = __shfl_sync(0xffffffffu, sj, j);
            float wt = __shfl_sync(0xffffffffu, wtj, j);
            float2 v = ((const float2*)(g_t1 + (size_t)s * 64))[lane];
            FMA2(t2, pack2(wt, wt), pack2(v.x, v.y));
        }
    }
    ((float2*)(g_t2 + (size_t)d * 64))[lane] = unpack2(t2);
}

// ---------------- final node kernel: cheb(3) + gcn + gat -------------------
__global__ __launch_bounds__(256) void kf(const float* __restrict__ x,
                                          const float* __restrict__ wts,
                                          const float* __restrict__ Wcheb,
                                          const float* __restrict__ bcheb,
                                          const float* __restrict__ Wgcn,
                                          const float* __restrict__ bgcn,
                                          const float* __restrict__ Wgat,
                                          const float* __restrict__ bgat,
                                          float* __restrict__ out, int N) {
    __shared__ __align__(16) float Wsm[4096];
    __shared__ float4 Xs[2048];
    int t = threadIdx.x;
    int tt = t & 127, half = t >> 7;
    int node = blockIdx.x * 128 + tt;
    bool act = node < N;
    float res[32];
    if (act) loadXs(Xs, (const float4*)(x + (size_t)node * 64), tt, half);
    loadW(Wsm, Wcheb, t);
    __syncthreads();
    if (act) {
#pragma unroll
        for (int c = 0; c < 2; c++) {
            int cc = half * 2 + c;
            unsigned long long a2[8];
            accInitBias(a2, bcheb + cc * 16);
            gemv16x2(Wsm, Xs, tt, cc * 16, a2);
            accOut(a2, res + c * 16);
        }
    }
    __syncthreads();
    if (act) loadXs(Xs, (const float4*)(g_t1 + (size_t)node * 64), tt, half);
    loadW(Wsm, Wcheb + 4096, t);
    __syncthreads();
    if (act) {
#pragma unroll
        for (int c = 0; c < 2; c++) {
            int cc = half * 2 + c;
            unsigned long long a2[8];
            accInitZero(a2);
            gemv16x2(Wsm, Xs, tt, cc * 16, a2);
            float acc[16];
            accOut(a2, acc);
#pragma unroll
            for (int j = 0; j < 16; j++) res[c * 16 + j] += acc[j];
        }
    }
    __syncthreads();
    if (act) {
        const float4* xr = (const float4*)(x + (size_t)node * 64);
        const float4* t2r = (const float4*)(g_t2 + (size_t)node * 64);
#pragma unroll
        for (int i = 0; i < 8; i++) {
            int k4 = half * 8 + i;
            float4 a = xr[k4];
            float4 b = t2r[k4];
            Xs[k4 * 128 + tt] = make_float4(-2.f * b.x - a.x, -2.f * b.y - a.y,
                                            -2.f * b.z - a.z, -2.f * b.w - a.w);
        }
    }
    loadW(Wsm, Wcheb + 8192, t);
    __syncthreads();
    float w2 = wts[2], w3 = wts[3], w4 = wts[4];
    if (act) {
#pragma unroll
        for (int c = 0; c < 2; c++) {
            int cc = half * 2 + c;
            unsigned long long a2[8];
            accInitZero(a2);
            gemv16x2(Wsm, Xs, tt, cc * 16, a2);
            float acc[16];
            accOut(a2, acc);
#pragma unroll
            for (int j = 0; j < 16; j++)
                res[c * 16 + j] = w4 * eluf(res[c * 16 + j] + acc[j]);
        }
    }
    __syncthreads();
    if (act) {
        float dinv = g_dinv[node];
        float di2 = dinv * dinv;
        const float4* xr = (const float4*)(x + (size_t)node * 64);
        const float4* gr = (const float4*)(g_gcnx + (size_t)node * 64);
#pragma unroll
        for (int i = 0; i < 8; i++) {
            int k4 = half * 8 + i;
            float4 a = xr[k4];
            float4 g = gr[k4];
            Xs[k4 * 128 + tt] = make_float4(g.x + di2 * a.x, g.y + di2 * a.y,
                                            g.z + di2 * a.z, g.w + di2 * a.w);
        }
    }
    loadW(Wsm, Wgcn, t);
    __syncthreads();
    if (act) {
#pragma unroll
        for (int c = 0; c < 2; c++) {
            int cc = half * 2 + c;
            unsigned long long a2[8];
            accInitBias(a2, bgcn + cc * 16);
            gemv16x2(Wsm, Xs, tt, cc * 16, a2);
            float acc[16];
            accOut(a2, acc);
#pragma unroll
            for (int j = 0; j < 16; j++) res[c * 16 + j] += w2 * eluf(acc[j]);
        }
    }
    __syncthreads();
    if (act) {
        float es = leakyf(g_el[node] + g_er[node]);
        float cs = expf(es);
        float invz = 1.f / (g_z[node] + 1e-16f);
        const float4* xr = (const float4*)(x + (size_t)node * 64);
        const float4* gr = (const float4*)(g_gatx + (size_t)node * 64);
#pragma unroll
        for (int i = 0; i < 8; i++) {
            int k4 = half * 8 + i;
            float4 a = xr[k4];
            float4 g = gr[k4];
            Xs[k4 * 128 + tt] = make_float4(invz * (g.x + cs * a.x),
                                            invz * (g.y + cs * a.y),
                                            invz * (g.z + cs * a.z),
                                            invz * (g.w + cs * a.w));
        }
    }
    loadW(Wsm, Wgat, t);
    __syncthreads();
    if (act) {
        float4* o4 = (float4*)(out + (size_t)node * 64);
#pragma unroll
        for (int c = 0; c < 2; c++) {
            int cc = half * 2 + c;
            unsigned long long a2[8];
            accInitBias(a2, bgat + cc * 16);
            gemv16x2(Wsm, Xs, tt, cc * 16, a2);
            float acc[16];
            accOut(a2, acc);
#pragma unroll
            for (int j = 0; j < 4; j++) {
                float4 ov = o4[cc * 4 + j];
                ov.x += res[c * 16 + 4 * j + 0] + w3 * eluf(acc[4 * j + 0]);
                ov.y += res[c * 16 + 4 * j + 1] + w3 * eluf(acc[4 * j + 1]);
                ov.z += res[c * 16 + 4 * j + 2] + w3 * eluf(acc[4 * j + 2]);
                ov.w += res[c * 16 + 4 * j + 3] + w3 * eluf(acc[4 * j + 3]);
                o4[cc * 4 + j] = ov;
            }
        }
    }
}

// ---------------- host launcher (graph-capture stream forking) --------------
extern "C" void kernel_launch(void* const* d_in, const int* in_sizes, int n_in,
                              void* d_out, int out_size) {
    static cudaStream_t s1 = nullptr;
    static cudaEvent_t ev_fork = nullptr, ev_a = nullptr, ev_b = nullptr, ev_j = nullptr;
    if (s1 == nullptr) {
        cudaStreamCreateWithFlags(&s1, cudaStreamNonBlocking);
        cudaEventCreateWithFlags(&ev_fork, cudaEventDisableTiming);
        cudaEventCreateWithFlags(&ev_a, cudaEventDisableTiming);
        cudaEventCreateWithFlags(&ev_b, cudaEventDisableTiming);
        cudaEventCreateWithFlags(&ev_j, cudaEventDisableTiming);
    }

    const float* x     = (const float*)d_in[0];
    const float* wts   = (const float*)d_in[1];
    const float* Wmlp  = (const float*)d_in[2];
    const float* bmlp  = (const float*)d_in[3];
    const float* Wl    = (const float*)d_in[4];
    const float* Wr    = (const float*)d_in[5];
    const float* bsage = (const float*)d_in[6];
    const float* Wgcn  = (const float*)d_in[7];
    const float* bgcn  = (const float*)d_in[8];
    const float* Wgat  = (const float*)d_in[9];
    const float* asrc  = (const float*)d_in[10];
    const float* adst  = (const float*)d_in[11];
    const float* bgat  = (const float*)d_in[12];
    const float* Wcheb = (const float*)d_in[13];
    const float* bcheb = (const float*)d_in[14];
    const float* Wgin  = (const float*)d_in[15];
    const float* bgin  = (const float*)d_in[16];
    const void*  eidx  = d_in[17];
    float* out = (float*)d_out;

    int N = in_sizes[0] / 64;
    if (N > NMAX) N = NMAX;
    int E = in_sizes[17] / 2;
    if (E > EMAX) E = EMAX;

    int nb_node = (N + 127) / 128;
    int nb_warp = (N * 32 + 255) / 256;
    int G = (N + 255) / 256;
    int nbE = (E + 255) / 256;

    cudaEventRecord(ev_fork, 0);
    cudaStreamWaitEvent(s1, ev_fork, 0);
    kvec<<<1, 64, 0, s1>>>(Wgat, asrc, adst);
    k1a<<<nb_node, 256, 0, s1>>>(x, wts, Wmlp, bmlp, Wr, bsage, out, N);
    cudaEventRecord(ev_a, s1);

    kinit<<<G, 256>>>((const int*)eidx, N);
    kconvert<<<nbE, 256>>>(eidx, E);
    kbsum<<<G, 256>>>(N);
    kbscan<<<1, 256>>>(G);
    kapply<<<G, 256>>>(N, E);
    kscatter<<<nbE, 256>>>(E);

    cudaStreamWaitEvent(0, ev_a, 0);
    kaggA<<<nb_warp, 256>>>(x, N);

    cudaEventRecord(ev_b, 0);
    cudaStreamWaitEvent(s1, ev_b, 0);
    k1b<<<nb_node, 256, 0, s1>>>(x, wts, Wl, Wgin, bgin, out, N);
    cudaEventRecord(ev_j, s1);

    kaggB<<<nb_warp, 256>>>(N);

    cudaStreamWaitEvent(0, ev_j, 0);
    kf<<<nb_node, 256>>>(x, wts, Wcheb, bcheb, Wgcn, bgcn, Wgat, bgat, out, N);
}